// round 13
// baseline (speedup 1.0000x reference)
#include <cuda_runtime.h>
#include <cuda_bf16.h>
#include <math.h>
#include <stdint.h>

#define B_ 4
#define C_ 8
#define S_ 512
#define E_ 512
#define H_ 8
#define HD_ 64
#define WINDOW 32
#define NTOK (B_*C_*S_)   /* 16384 */

// input splits: 3 regions (q,k,v inputs); attn ctx reuses region 0
static __device__ __nv_bfloat16 g_inh[(size_t)3 * NTOK * E_];
static __device__ __nv_bfloat16 g_inl[(size_t)3 * NTOK * E_];
// weight splits: 4 regions (Wq,Wk,Wv,Wo)
static __device__ __nv_bfloat16 g_Wh4[(size_t)4 * E_ * E_];
static __device__ __nv_bfloat16 g_Wl4[(size_t)4 * E_ * E_];
// projected q/k/v hi/lo
static __device__ __nv_bfloat16 g_qh[(size_t)NTOK * E_];
static __device__ __nv_bfloat16 g_ql[(size_t)NTOK * E_];
static __device__ __nv_bfloat16 g_kh[(size_t)NTOK * E_];
static __device__ __nv_bfloat16 g_kl[(size_t)NTOK * E_];
static __device__ __nv_bfloat16 g_vh[(size_t)NTOK * E_];
static __device__ __nv_bfloat16 g_vl[(size_t)NTOK * E_];

// ============================ helpers ======================================
__device__ __forceinline__ uint32_t smem_to_u32(const void* p) {
    uint32_t a;
    asm("{ .reg .u64 t; cvta.to.shared.u64 t, %1; cvt.u32.u64 %0, t; }"
        : "=r"(a) : "l"(p));
    return a;
}
__device__ __forceinline__ void cp16(uint32_t dst, const void* src) {
    asm volatile("cp.async.cg.shared.global [%0], [%1], 16;"
                 :: "r"(dst), "l"(src) : "memory");
}
__device__ __forceinline__ void ldsm4(uint32_t* r, uint32_t addr) {
    asm volatile("ldmatrix.sync.aligned.m8n8.x4.shared.b16 {%0,%1,%2,%3}, [%4];"
                 : "=r"(r[0]), "=r"(r[1]), "=r"(r[2]), "=r"(r[3]) : "r"(addr));
}
__device__ __forceinline__ void ldsm4t(uint32_t* r, uint32_t addr) {
    asm volatile("ldmatrix.sync.aligned.m8n8.x4.trans.shared.b16 {%0,%1,%2,%3}, [%4];"
                 : "=r"(r[0]), "=r"(r[1]), "=r"(r[2]), "=r"(r[3]) : "r"(addr));
}
__device__ __forceinline__ void mma16816(float* d, const uint32_t* a,
                                         uint32_t b0, uint32_t b1) {
    asm volatile("mma.sync.aligned.m16n8k16.row.col.f32.bf16.bf16.f32 "
                 "{%0,%1,%2,%3}, {%4,%5,%6,%7}, {%8,%9}, {%0,%1,%2,%3};"
                 : "+f"(d[0]), "+f"(d[1]), "+f"(d[2]), "+f"(d[3])
                 : "r"(a[0]), "r"(a[1]), "r"(a[2]), "r"(a[3]), "r"(b0), "r"(b1));
}
__device__ __forceinline__ uint32_t swz(int row, int c) {
    return (uint32_t)(row * 64 + ((c ^ ((row >> 1) & 3)) << 4));
}
__device__ __forceinline__ uint32_t swz128(int row, int c) {
    return (uint32_t)(row * 128 + ((c ^ (row & 7)) << 4));
}
__device__ __forceinline__ void split2(float x, uint32_t& h, uint32_t& l) {
    __nv_bfloat16 hb = __float2bfloat16(x);
    __nv_bfloat16 lb = __float2bfloat16(x - __bfloat162float(hb));
    h = (uint32_t)__bfloat16_as_ushort(hb);
    l = (uint32_t)__bfloat16_as_ushort(lb);
}

// ============================ batched split kernels ========================
struct SplitIn3 { const float4* src[3]; uint2* hi[3]; uint2* lo[3]; };
struct SplitW4  { const float4* src[4]; uint2* hi[4]; uint2* lo[4]; };

__device__ __forceinline__ void split_one(const float4* src, uint2* hi,
                                          uint2* lo, int i) {
    float4 v = src[i];
    uint32_t h[4], l[4];
    split2(v.x, h[0], l[0]); split2(v.y, h[1], l[1]);
    split2(v.z, h[2], l[2]); split2(v.w, h[3], l[3]);
    uint2 ph, pl;
    ph.x = h[0] | (h[1] << 16); ph.y = h[2] | (h[3] << 16);
    pl.x = l[0] | (l[1] << 16); pl.y = l[2] | (l[3] << 16);
    hi[i] = ph; lo[i] = pl;
}
__global__ __launch_bounds__(256) void split_in3(SplitIn3 p) {
    const int z = blockIdx.z;
    const int i = blockIdx.x * 512 + threadIdx.x;
    split_one(p.src[z], p.hi[z], p.lo[z], i);
    split_one(p.src[z], p.hi[z], p.lo[z], i + 256);
}
__global__ __launch_bounds__(256) void split_w4(SplitW4 p) {
    const int z = blockIdx.z;
    const int i = blockIdx.x * 512 + threadIdx.x;
    split_one(p.src[z], p.hi[z], p.lo[z], i);
    split_one(p.src[z], p.hi[z], p.lo[z], i + 256);
}

// ============================ HMMA GEMM ====================================
// 3-stage cp.async ring: compute stage s overlaps loads of s+1 AND s+2.
#define GM 128
#define GN 128
#define KCH 32
#define NST (E_/KCH)             /* 16 */
#define TILE_B (128*64)
#define STAGE_B (4*TILE_B)       /* 32 KB */
#define GSMEM (3*STAGE_B)        /* 96 KB -> 2 CTAs/SM */

__device__ __forceinline__ void gemm_issue_stage(
    uint32_t sb, int s, int m0, int n0, int tid,
    const __nv_bfloat16* Ah, const __nv_bfloat16* Al,
    const __nv_bfloat16* Wh, const __nv_bfloat16* Wl)
{
    const uint32_t base = sb + (uint32_t)(s % 3) * STAGE_B;
    const int k0 = s * KCH;
#pragma unroll
    for (int q = 0; q < 2; q++) {
        const int id  = tid * 2 + q;
        const int row = id >> 2;
        const int c   = id & 3;
        const uint32_t d = base + swz(row, c);
        const size_t ga = (size_t)(m0 + row) * E_ + k0 + c * 8;
        const size_t gw = (size_t)(n0 + row) * E_ + k0 + c * 8;
        cp16(d,              Ah + ga);
        cp16(d + TILE_B,     Al + ga);
        cp16(d + 2 * TILE_B, Wh + gw);
        cp16(d + 3 * TILE_B, Wl + gw);
    }
    asm volatile("cp.async.commit_group;" ::: "memory");
}

__device__ __forceinline__ void gemm_core(
    const __nv_bfloat16* __restrict__ Ah, const __nv_bfloat16* __restrict__ Al,
    const __nv_bfloat16* __restrict__ Wh, const __nv_bfloat16* __restrict__ Wl,
    const float* __restrict__ bias, float* __restrict__ out,
    __nv_bfloat16* __restrict__ outh, __nv_bfloat16* __restrict__ outl,
    int mode, char* gsm)
{
    const uint32_t sb = smem_to_u32(gsm);
    const int tid  = threadIdx.x;
    const int lane = tid & 31;
    const int wid  = tid >> 5;
    const int wm   = wid & 1;
    const int wn   = wid >> 1;
    const int m0 = blockIdx.x * GM;
    const int n0 = blockIdx.y * GN;

    float acc[4][4][4];
#pragma unroll
    for (int a = 0; a < 4; a++)
#pragma unroll
        for (int b = 0; b < 4; b++)
#pragma unroll
            for (int c = 0; c < 4; c++) acc[a][b][c] = 0.f;

    gemm_issue_stage(sb, 0, m0, n0, tid, Ah, Al, Wh, Wl);
    gemm_issue_stage(sb, 1, m0, n0, tid, Ah, Al, Wh, Wl);
    gemm_issue_stage(sb, 2, m0, n0, tid, Ah, Al, Wh, Wl);

    for (int s = 0; s < NST; s++) {
        // retire stage s (pending: s, s+1, s+2 while all issued)
        if (s < NST - 2)      asm volatile("cp.async.wait_group 2;" ::: "memory");
        else if (s == NST - 2) asm volatile("cp.async.wait_group 1;" ::: "memory");
        else                   asm volatile("cp.async.wait_group 0;" ::: "memory");
        __syncthreads();

        const uint32_t aB = sb + (uint32_t)(s % 3) * STAGE_B;
        const uint32_t wB = aB + 2 * TILE_B;

#pragma unroll
        for (int ks = 0; ks < 2; ks++) {
            uint32_t af[4][4], whf[2][4], wlf[2][4];
#pragma unroll
            for (int mt = 0; mt < 4; mt++) {
                const int row = wm * 64 + mt * 16 + (lane & 15);
                const int c   = ks * 2 + (lane >> 4);
                ldsm4(af[mt], aB + swz(row, c));
            }
#pragma unroll
            for (int np = 0; np < 2; np++) {
                const int row = wn * 32 + np * 16 + (lane & 7) + ((lane >> 4) & 1) * 8;
                const int c   = ks * 2 + ((lane >> 3) & 1);
                const uint32_t addr = wB + swz(row, c);
                ldsm4(whf[np], addr);
                ldsm4(wlf[np], addr + TILE_B);
            }
#pragma unroll
            for (int mt = 0; mt < 4; mt++)
#pragma unroll
                for (int nt = 0; nt < 4; nt++) {
                    const int np = nt >> 1, o = (nt & 1) * 2;
                    mma16816(acc[mt][nt], af[mt], whf[np][o], whf[np][o + 1]);
                    mma16816(acc[mt][nt], af[mt], wlf[np][o], wlf[np][o + 1]);
                }
#pragma unroll
            for (int mt = 0; mt < 4; mt++) {
                const int row = wm * 64 + mt * 16 + (lane & 15);
                const int c   = ks * 2 + (lane >> 4);
                ldsm4(af[mt], aB + TILE_B + swz(row, c));
            }
#pragma unroll
            for (int mt = 0; mt < 4; mt++)
#pragma unroll
                for (int nt = 0; nt < 4; nt++) {
                    const int np = nt >> 1, o = (nt & 1) * 2;
                    mma16816(acc[mt][nt], af[mt], whf[np][o], whf[np][o + 1]);
                }
        }
        __syncthreads();
        if (s + 3 < NST)
            gemm_issue_stage(sb, s + 3, m0, n0, tid, Ah, Al, Wh, Wl);
    }

#pragma unroll
    for (int nt = 0; nt < 4; nt++) {
        const int gn = n0 + wn * 32 + nt * 8 + (lane & 3) * 2;
        const float2 bv = *(const float2*)(bias + gn);
#pragma unroll
        for (int mt = 0; mt < 4; mt++) {
            const int gm = m0 + wm * 64 + mt * 16 + (lane >> 2);
            float x0 = acc[mt][nt][0] + bv.x, x1 = acc[mt][nt][1] + bv.y;
            float x2 = acc[mt][nt][2] + bv.x, x3 = acc[mt][nt][3] + bv.y;
            if (mode == 0) {
                *(float2*)(out + (size_t)gm * E_ + gn)       = make_float2(x0, x1);
                *(float2*)(out + (size_t)(gm + 8) * E_ + gn) = make_float2(x2, x3);
            } else {
                uint32_t h0, l0, h1, l1, h2, l2, h3, l3;
                split2(x0, h0, l0); split2(x1, h1, l1);
                split2(x2, h2, l2); split2(x3, h3, l3);
                *(uint32_t*)(outh + (size_t)gm * E_ + gn)       = h0 | (h1 << 16);
                *(uint32_t*)(outl + (size_t)gm * E_ + gn)       = l0 | (l1 << 16);
                *(uint32_t*)(outh + (size_t)(gm + 8) * E_ + gn) = h2 | (h3 << 16);
                *(uint32_t*)(outl + (size_t)(gm + 8) * E_ + gn) = l2 | (l3 << 16);
            }
        }
    }
}

struct GemmB3 {
    const __nv_bfloat16* Ah[3]; const __nv_bfloat16* Al[3];
    const __nv_bfloat16* Wh[3]; const __nv_bfloat16* Wl[3];
    const float* bias[3];
    __nv_bfloat16* outh[3]; __nv_bfloat16* outl[3];
};

__global__ __launch_bounds__(256) void gemm_mma_b3(GemmB3 p) {
    extern __shared__ char gsm[];
    const int z = blockIdx.z;
    gemm_core(p.Ah[z], p.Al[z], p.Wh[z], p.Wl[z], p.bias[z],
              nullptr, p.outh[z], p.outl[z], 1, gsm);
}

__global__ __launch_bounds__(256) void gemm_mma_single(
    const __nv_bfloat16* Ah, const __nv_bfloat16* Al,
    const __nv_bfloat16* Wh, const __nv_bfloat16* Wl,
    const float* bias, float* out)
{
    extern __shared__ char gsm[];
    gemm_core(Ah, Al, Wh, Wl, bias, out, nullptr, nullptr, 0, gsm);
}

// ============================ sparse attention =============================
#define QT 64
#define SCLD 200
#define ATTN_SMEM (24576 + QT*SCLD*4)   /* 75776 B -> 3 CTAs/SM */

__global__ __launch_bounds__(256) void attn_tiled(
    float* __restrict__ attn_out,
    __nv_bfloat16* __restrict__ ctx_hi, __nv_bfloat16* __restrict__ ctx_lo,
    const __nv_bfloat16* __restrict__ qh, const __nv_bfloat16* __restrict__ ql,
    const __nv_bfloat16* __restrict__ kh, const __nv_bfloat16* __restrict__ kl,
    const __nv_bfloat16* __restrict__ vh, const __nv_bfloat16* __restrict__ vl)
{
    extern __shared__ char smraw[];
    const uint32_t sb = smem_to_u32(smraw);
    float* sc = (float*)(smraw + 24576);

    const int tid  = threadIdx.x;
    const int lane = tid & 31;
    const int wid  = tid >> 5;
    const int wm   = wid & 3;
    const int wn   = wid >> 2;
    const int qt   = blockIdx.x;
    const int h    = blockIdx.y;
    const int z    = blockIdx.z;

    const int q0     = qt * QT;
    const int we     = q0 + QT - 1;
    const int wstart = (q0 >= WINDOW) ? (q0 - WINDOW) : 0;
    const int Ncs    = wstart >> 2;
    const int NU     = Ncs + (we - wstart + 1);
    const int nch    = (NU + 31) >> 5;

    const size_t tokBase = ((size_t)z * S_) * E_ + h * HD_;

    for (int t = tid; t < 512; t += 256) {
        const int r = t >> 3, c = t & 7;
        const size_t g = tokBase + (size_t)(q0 + r) * E_ + c * 8;
        const uint32_t d = sb + swz128(r, c);
        cp16(d, qh + g);
        cp16(d + 8192, ql + g);
    }
    asm volatile("cp.async.commit_group;" ::: "memory");

    const float NEGINF = __int_as_float(0xff800000);
    for (int ch = 0; ch < nch; ch++) {
        const int uc0 = ch << 5;
        for (int t = tid; t < 256; t += 256) {
            const int r = t >> 3, c = t & 7;
            const int u = uc0 + r;
            int j = 0;
            if (u < NU) j = (u < Ncs) ? (u << 2) : (wstart + u - Ncs);
            const size_t g = tokBase + (size_t)j * E_ + c * 8;
            const uint32_t d = sb + 16384 + swz128(r, c);
            cp16(d, kh + g);
            cp16(d + 4096, kl + g);
        }
        asm volatile("cp.async.commit_group;" ::: "memory");
        asm volatile("cp.async.wait_group 0;" ::: "memory");
        __syncthreads();

        float acc[2][4];
#pragma unroll
        for (int a = 0; a < 2; a++)
#pragma unroll
            for (int b = 0; b < 4; b++) acc[a][b] = 0.f;

#pragma unroll
        for (int kk = 0; kk < 4; kk++) {
            uint32_t ah[4], al[4], bh[4], bl[4];
            {
                const int row = wm * 16 + (lane & 15);
                const int c   = kk * 2 + (lane >> 4);
                ldsm4(ah, sb + swz128(row, c));
                ldsm4(al, sb + 8192 + swz128(row, c));
            }
            {
                const int row = wn * 16 + (lane & 7) + ((lane >> 4) & 1) * 8;
                const int c   = kk * 2 + ((lane >> 3) & 1);
                ldsm4(bh, sb + 16384 + swz128(row, c));
                ldsm4(bl, sb + 20480 + swz128(row, c));
            }
#pragma unroll
            for (int nt = 0; nt < 2; nt++) {
                const int o = nt * 2;
                mma16816(acc[nt], ah, bh[o], bh[o + 1]);
                mma16816(acc[nt], ah, bl[o], bl[o + 1]);
                mma16816(acc[nt], al, bh[o], bh[o + 1]);
            }
        }

        const int r0 = wm * 16 + (lane >> 2);
#pragma unroll
        for (int nt = 0; nt < 2; nt++) {
            const int uc = uc0 + wn * 16 + nt * 8 + (lane & 3) * 2;
            if (uc < NU) {
                const int ja = (uc < Ncs) ? (uc << 2) : (wstart + uc - Ncs);
                const int jb = (uc + 1 < Ncs) ? ((uc + 1) << 2)
                                              : (wstart + uc + 1 - Ncs);
#pragma unroll
                for (int h2 = 0; h2 < 2; h2++) {
                    const int row = r0 + h2 * 8;
                    const int i   = q0 + row;
                    const bool oka = (ja <= i) && ((ja >= i - WINDOW) || ((ja & 3) == 0));
                    const bool okb = (jb <= i) && ((jb >= i - WINDOW) || ((jb & 3) == 0));
                    float2 st;
                    st.x = oka ? acc[nt][h2 * 2 + 0] * 0.125f : NEGINF;
                    st.y = okb ? acc[nt][h2 * 2 + 1] * 0.125f : NEGINF;
                    *(float2*)(sc + row * SCLD + uc) = st;
                }
            }
        }
        __syncthreads();
    }

    // ---- softmax (vectorized, NU % 8 == 0) --------------------------------
    {
        const int row = tid >> 2;
        const int ln  = tid & 3;
        float* srow = sc + row * SCLD;
        const int nv = NU >> 2;
        float m = NEGINF;
        for (int q = ln; q < nv; q += 4) {
            const float4 v = ((const float4*)srow)[q];
            m = fmaxf(m, fmaxf(fmaxf(v.x, v.y), fmaxf(v.z, v.w)));
        }
        m = fmaxf(m, __shfl_xor_sync(0xffffffffu, m, 1));
        m = fmaxf(m, __shfl_xor_sync(0xffffffffu, m, 2));
        float sum = 0.f;
        for (int q = ln; q < nv; q += 4) {
            float4 v = ((const float4*)srow)[q];
            v.x = __expf(v.x - m); v.y = __expf(v.y - m);
            v.z = __expf(v.z - m); v.w = __expf(v.w - m);
            ((float4*)srow)[q] = v;
            sum += v.x + v.y + v.z + v.w;
        }
        sum += __shfl_xor_sync(0xffffffffu, sum, 1);
        sum += __shfl_xor_sync(0xffffffffu, sum, 2);
        const float inv = 1.f / sum;
        for (int q = ln; q < nv; q += 4) {
            float4 v = ((const float4*)srow)[q];
            v.x *= inv; v.y *= inv; v.z *= inv; v.w *= inv;
            ((float4*)srow)[q] = v;
        }
    }
    __syncthreads();

    // ---- dense attn write ([B,H,C,S,S]) -----------------------------------
    {
        const int b = z / C_, c = z % C_;
        float* abase = attn_out +
            ((((size_t)(b * H_ + h) * C_ + c) * S_ + q0) * (size_t)S_);
        for (int t = tid; t < QT * (S_ / 4); t += 256) {
            const int r  = t >> 7;
            const int j0 = (t & 127) << 2;
            const float* srow = sc + r * SCLD;
            float4 v = make_float4(0.f, 0.f, 0.f, 0.f);
            if (j0 <= we) {
                if (j0 >= wstart)
                    v = *(const float4*)(srow + Ncs + j0 - wstart);
                else
                    v.x = srow[j0 >> 2];
            }
            *(float4*)(abase + (size_t)r * S_ + j0) = v;
        }
    }

    // ---- context: HMMA bf16x3, 32-u chunks --------------------------------
    float cacc[4][4];
#pragma unroll
    for (int a = 0; a < 4; a++)
#pragma unroll
        for (int b = 0; b < 4; b++) cacc[a][b] = 0.f;

    for (int ch = 0; ch < nch; ch++) {
        const int uc0 = ch << 5;
        __syncthreads();

        for (int t = tid; t < 256; t += 256) {
            const int r = t >> 3, c = t & 7;
            const int u = uc0 + r;
            int j = 0;
            if (u < NU) j = (u < Ncs) ? (u << 2) : (wstart + u - Ncs);
            const size_t g = tokBase + (size_t)j * E_ + c * 8;
            const uint32_t d = sb + 16384 + swz128(r, c);
            cp16(d, vh + g);
            cp16(d + 4096, vl + g);
        }
        asm volatile("cp.async.commit_group;" ::: "memory");

        for (int t = tid; t < 256; t += 256) {
            const int row = t >> 2, cg = t & 3;
            const int u0 = uc0 + cg * 8;
            float4 pa = make_float4(0.f, 0.f, 0.f, 0.f);
            float4 pb = make_float4(0.f, 0.f, 0.f, 0.f);
            if (u0 < NU) {
                pa = *(const float4*)(sc + row * SCLD + u0);
                pb = *(const float4*)(sc + row * SCLD + u0 + 4);
            }
            const float pv[8] = {pa.x, pa.y, pa.z, pa.w, pb.x, pb.y, pb.z, pb.w};
            uint32_t hp[4], lp[4];
#pragma unroll
            for (int pr = 0; pr < 4; pr++) {
                uint32_t h0, l0, h1, l1;
                split2(pv[pr * 2 + 0], h0, l0);
                split2(pv[pr * 2 + 1], h1, l1);
                hp[pr] = h0 | (h1 << 16);
                lp[pr] = l0 | (l1 << 16);
            }
            *(uint4*)(smraw + swz(row, cg))        = make_uint4(hp[0], hp[1], hp[2], hp[3]);
            *(uint4*)(smraw + 8192 + swz(row, cg)) = make_uint4(lp[0], lp[1], lp[2], lp[3]);
        }
        asm volatile("cp.async.wait_group 0;" ::: "memory");
        __syncthreads();

#pragma unroll
        for (int kk = 0; kk < 2; kk++) {
            uint32_t ah[4], al[4], bh[2][4], bl[2][4];
            {
                const int row = wm * 16 + (lane & 15);
                const int c   = kk * 2 + (lane >> 4);
                ldsm4(ah, sb + swz(row, c));
                ldsm4(al, sb + 8192 + swz(row, c));
            }
#pragma unroll
            for (int np = 0; np < 2; np++) {
                const int row = kk * 16 + (lane & 15);
                const int c   = wn * 4 + np * 2 + (lane >> 4);
                ldsm4t(bh[np], sb + 16384 + swz128(row, c));
                ldsm4t(bl[np], sb + 20480 + swz128(row, c));
            }
#pragma unroll
            for (int nt = 0; nt < 4; nt++) {
                const int np = nt >> 1, o = (nt & 1) * 2;
                mma16816(cacc[nt], ah, bh[np][o], bh[np][o + 1]);
                mma16816(cacc[nt], ah, bl[np][o], bl[np][o + 1]);
                mma16816(cacc[nt], al, bh[np][o], bh[np][o + 1]);
            }
        }
    }

    // ---- epilogue: ctx fragments -> bf16 hi/lo ----------------------------
    {
        const int r0 = wm * 16 + (lane >> 2);
#pragma unroll
        for (int nt = 0; nt < 4; nt++) {
            const int d0 = wn * 32 + nt * 8 + (lane & 3) * 2;
#pragma unroll
            for (int h2 = 0; h2 < 2; h2++) {
                const int i = q0 + r0 + h2 * 8;
                const size_t base = tokBase + (size_t)i * E_ + d0;
                uint32_t h0, l0, h1, l1;
                split2(cacc[nt][h2 * 2 + 0], h0, l0);
                split2(cacc[nt][h2 * 2 + 1], h1, l1);
                *(uint32_t*)(ctx_hi + base) = h0 | (h1 << 16);
                *(uint32_t*)(ctx_lo + base) = l0 | (l1 << 16);
            }
        }
    }
}

// ===========================================================================
extern "C" void kernel_launch(void* const* d_in, const int* in_sizes, int n_in,
                              void* d_out, int out_size)
{
    const float* query = (const float*)d_in[0];
    const float* key_  = (const float*)d_in[1];
    const float* value = (const float*)d_in[2];
    const float* Wq = (const float*)d_in[3];
    const float* bq = (const float*)d_in[4];
    const float* Wk = (const float*)d_in[5];
    const float* bk = (const float*)d_in[6];
    const float* Wv = (const float*)d_in[7];
    const float* bv = (const float*)d_in[8];
    const float* Wo = (const float*)d_in[9];
    const float* bo = (const float*)d_in[10];

    float* out  = (float*)d_out;
    float* attn = out + (size_t)NTOK * E_;

    __nv_bfloat16 *inh, *inl, *Wh4, *Wl4, *qh, *ql, *kh, *kl, *vh, *vl;
    cudaGetSymbolAddress((void**)&inh, g_inh);
    cudaGetSymbolAddress((void**)&inl, g_inl);
    cudaGetSymbolAddress((void**)&Wh4, g_Wh4);
    cudaGetSymbolAddress((void**)&Wl4, g_Wl4);
    cudaGetSymbolAddress((void**)&qh, g_qh);
    cudaGetSymbolAddress((void**)&ql, g_ql);
    cudaGetSymbolAddress((void**)&kh, g_kh);
    cudaGetSymbolAddress((void**)&kl, g_kl);
    cudaGetSymbolAddress((void**)&vh, g_vh);
    cudaGetSymbolAddress((void**)&vl, g_vl);

    cudaFuncSetAttribute(attn_tiled,
        cudaFuncAttributeMaxDynamicSharedMemorySize, ATTN_SMEM);
    cudaFuncSetAttribute(gemm_mma_b3,
        cudaFuncAttributeMaxDynamicSharedMemorySize, GSMEM);
    cudaFuncSetAttribute(gemm_mma_single,
        cudaFuncAttributeMaxDynamicSharedMemorySize, GSMEM);

    const size_t NE = (size_t)NTOK * E_;
    const size_t WE = (size_t)E_ * E_;
    const int NA4 = NTOK * E_ / 4;
    const int NW4 = E_ * E_ / 4;

    SplitIn3 si;
    si.src[0] = (const float4*)query; si.src[1] = (const float4*)key_;
    si.src[2] = (const float4*)value;
    for (int z = 0; z < 3; z++) {
        si.hi[z] = (uint2*)(inh + z * NE);
        si.lo[z] = (uint2*)(inl + z * NE);
    }
    split_in3<<<dim3(NA4 / 512, 1, 3), 256>>>(si);

    SplitW4 sw;
    sw.src[0] = (const float4*)Wq; sw.src[1] = (const float4*)Wk;
    sw.src[2] = (const float4*)Wv; sw.src[3] = (const float4*)Wo;
    for (int z = 0; z < 4; z++) {
        sw.hi[z] = (uint2*)(Wh4 + z * WE);
        sw.lo[z] = (uint2*)(Wl4 + z * WE);
    }
    split_w4<<<dim3(NW4 / 512, 1, 4), 256>>>(sw);

    GemmB3 gb;
    __nv_bfloat16* oh[3] = {qh, kh, vh};
    __nv_bfloat16* ol[3] = {ql, kl, vl};
    const float* bs[3] = {bq, bk, bv};
    for (int z = 0; z < 3; z++) {
        gb.Ah[z] = inh + z * NE;  gb.Al[z] = inl + z * NE;
        gb.Wh[z] = Wh4 + z * WE;  gb.Wl[z] = Wl4 + z * WE;
        gb.bias[z] = bs[z];
        gb.outh[z] = oh[z];  gb.outl[z] = ol[z];
    }
    gemm_mma_b3<<<dim3(NTOK / GM, E_ / GN, 3), 256, GSMEM>>>(gb);

    dim3 agrid(S_ / QT, H_, B_ * C_);
    attn_tiled<<<agrid, 256, ATTN_SMEM>>>(attn, inh, inl,
                                          qh, ql, kh, kl, vh, vl);

    gemm_mma_single<<<dim3(NTOK / GM, E_ / GN), 256, GSMEM>>>(
        inh, inl, Wh4 + 3 * WE, Wl4 + 3 * WE, bo, out);
}

// round 14
// speedup vs baseline: 1.2160x; 1.2160x over previous
#include <cuda_runtime.h>
#include <cuda_bf16.h>
#include <math.h>
#include <stdint.h>

#define B_ 4
#define C_ 8
#define S_ 512
#define E_ 512
#define H_ 8
#define HD_ 64
#define WINDOW 32
#define NTOK (B_*C_*S_)   /* 16384 */

// ctx split (written by attn, read by O-projection)
static __device__ __nv_bfloat16 g_inh[(size_t)NTOK * E_];
static __device__ __nv_bfloat16 g_inl[(size_t)NTOK * E_];
// weight splits: 4 regions (Wq,Wk,Wv,Wo)
static __device__ __nv_bfloat16 g_Wh4[(size_t)4 * E_ * E_];
static __device__ __nv_bfloat16 g_Wl4[(size_t)4 * E_ * E_];
// projected q/k/v hi/lo
static __device__ __nv_bfloat16 g_qh[(size_t)NTOK * E_];
static __device__ __nv_bfloat16 g_ql[(size_t)NTOK * E_];
static __device__ __nv_bfloat16 g_kh[(size_t)NTOK * E_];
static __device__ __nv_bfloat16 g_kl[(size_t)NTOK * E_];
static __device__ __nv_bfloat16 g_vh[(size_t)NTOK * E_];
static __device__ __nv_bfloat16 g_vl[(size_t)NTOK * E_];

// ============================ helpers ======================================
__device__ __forceinline__ uint32_t smem_to_u32(const void* p) {
    uint32_t a;
    asm("{ .reg .u64 t; cvta.to.shared.u64 t, %1; cvt.u32.u64 %0, t; }"
        : "=r"(a) : "l"(p));
    return a;
}
__device__ __forceinline__ void cp16(uint32_t dst, const void* src) {
    asm volatile("cp.async.cg.shared.global [%0], [%1], 16;"
                 :: "r"(dst), "l"(src) : "memory");
}
__device__ __forceinline__ void ldsm4(uint32_t* r, uint32_t addr) {
    asm volatile("ldmatrix.sync.aligned.m8n8.x4.shared.b16 {%0,%1,%2,%3}, [%4];"
                 : "=r"(r[0]), "=r"(r[1]), "=r"(r[2]), "=r"(r[3]) : "r"(addr));
}
__device__ __forceinline__ void ldsm4t(uint32_t* r, uint32_t addr) {
    asm volatile("ldmatrix.sync.aligned.m8n8.x4.trans.shared.b16 {%0,%1,%2,%3}, [%4];"
                 : "=r"(r[0]), "=r"(r[1]), "=r"(r[2]), "=r"(r[3]) : "r"(addr));
}
__device__ __forceinline__ void mma16816(float* d, const uint32_t* a,
                                         uint32_t b0, uint32_t b1) {
    asm volatile("mma.sync.aligned.m16n8k16.row.col.f32.bf16.bf16.f32 "
                 "{%0,%1,%2,%3}, {%4,%5,%6,%7}, {%8,%9}, {%0,%1,%2,%3};"
                 : "+f"(d[0]), "+f"(d[1]), "+f"(d[2]), "+f"(d[3])
                 : "r"(a[0]), "r"(a[1]), "r"(a[2]), "r"(a[3]), "r"(b0), "r"(b1));
}
__device__ __forceinline__ uint32_t swz(int row, int c) {
    return (uint32_t)(row * 64 + ((c ^ ((row >> 1) & 3)) << 4));
}
__device__ __forceinline__ uint32_t swz128(int row, int c) {
    return (uint32_t)(row * 128 + ((c ^ (row & 7)) << 4));
}
__device__ __forceinline__ void split2(float x, uint32_t& h, uint32_t& l) {
    __nv_bfloat16 hb = __float2bfloat16(x);
    __nv_bfloat16 lb = __float2bfloat16(x - __bfloat162float(hb));
    h = (uint32_t)__bfloat16_as_ushort(hb);
    l = (uint32_t)__bfloat16_as_ushort(lb);
}

// ============================ weight split kernel ==========================
struct SplitW4 { const float4* src[4]; uint2* hi[4]; uint2* lo[4]; };

__device__ __forceinline__ void split_one(const float4* src, uint2* hi,
                                          uint2* lo, int i) {
    float4 v = src[i];
    uint32_t h[4], l[4];
    split2(v.x, h[0], l[0]); split2(v.y, h[1], l[1]);
    split2(v.z, h[2], l[2]); split2(v.w, h[3], l[3]);
    uint2 ph, pl;
    ph.x = h[0] | (h[1] << 16); ph.y = h[2] | (h[3] << 16);
    pl.x = l[0] | (l[1] << 16); pl.y = l[2] | (l[3] << 16);
    hi[i] = ph; lo[i] = pl;
}
__global__ __launch_bounds__(256) void split_w4(SplitW4 p) {
    const int z = blockIdx.z;
    const int i = blockIdx.x * 512 + threadIdx.x;
    split_one(p.src[z], p.hi[z], p.lo[z], i);
    split_one(p.src[z], p.hi[z], p.lo[z], i + 256);
}

// ============================ HMMA GEMM ====================================
#define GM 128
#define GN 128
#define KCH 32
#define NST (E_/KCH)             /* 16 */
#define TILE_B (128*64)          /* 8192  */
#define STAGE_B (4*TILE_B)       /* 32768 (pre-split A path) */
#define GSMEM (2*STAGE_B)        /* 65536 */
#define AF32_B 16384             /* fp32 A tile: 128 x 32 x 4B */
#define STAGE_F (AF32_B + 4*TILE_B)  /* 49152 (fp32-A path) */
#define GSMEM_F (2*STAGE_F)      /* 98304 */

// ---- shared mainloop (ldsm + mma) over tiles at given smem offsets --------
struct Frag { float acc[4][4][4]; };

__device__ __forceinline__ void gemm_stage_math(
    Frag& F, uint32_t ahB, uint32_t alB, uint32_t whB, uint32_t wlB,
    int lane, int wm, int wn)
{
#pragma unroll
    for (int ks = 0; ks < 2; ks++) {
        uint32_t af[4][4], whf[2][4], wlf[2][4];
#pragma unroll
        for (int mt = 0; mt < 4; mt++) {
            const int row = wm * 64 + mt * 16 + (lane & 15);
            const int c   = ks * 2 + (lane >> 4);
            ldsm4(af[mt], ahB + swz(row, c));
        }
#pragma unroll
        for (int np = 0; np < 2; np++) {
            const int row = wn * 32 + np * 16 + (lane & 7) + ((lane >> 4) & 1) * 8;
            const int c   = ks * 2 + ((lane >> 3) & 1);
            ldsm4(whf[np], whB + swz(row, c));
            ldsm4(wlf[np], wlB + swz(row, c));
        }
#pragma unroll
        for (int mt = 0; mt < 4; mt++)
#pragma unroll
            for (int nt = 0; nt < 4; nt++) {
                const int np = nt >> 1, o = (nt & 1) * 2;
                mma16816(F.acc[mt][nt], af[mt], whf[np][o], whf[np][o + 1]);
                mma16816(F.acc[mt][nt], af[mt], wlf[np][o], wlf[np][o + 1]);
            }
#pragma unroll
        for (int mt = 0; mt < 4; mt++) {
            const int row = wm * 64 + mt * 16 + (lane & 15);
            const int c   = ks * 2 + (lane >> 4);
            ldsm4(af[mt], alB + swz(row, c));
        }
#pragma unroll
        for (int mt = 0; mt < 4; mt++)
#pragma unroll
            for (int nt = 0; nt < 4; nt++) {
                const int np = nt >> 1, o = (nt & 1) * 2;
                mma16816(F.acc[mt][nt], af[mt], whf[np][o], whf[np][o + 1]);
            }
    }
}

__device__ __forceinline__ void gemm_epilogue(
    Frag& F, const float* bias, float* out,
    __nv_bfloat16* outh, __nv_bfloat16* outl, int mode,
    int m0, int n0, int lane, int wm, int wn)
{
#pragma unroll
    for (int nt = 0; nt < 4; nt++) {
        const int gn = n0 + wn * 32 + nt * 8 + (lane & 3) * 2;
        const float2 bv = *(const float2*)(bias + gn);
#pragma unroll
        for (int mt = 0; mt < 4; mt++) {
            const int gm = m0 + wm * 64 + mt * 16 + (lane >> 2);
            float x0 = F.acc[mt][nt][0] + bv.x, x1 = F.acc[mt][nt][1] + bv.y;
            float x2 = F.acc[mt][nt][2] + bv.x, x3 = F.acc[mt][nt][3] + bv.y;
            if (mode == 0) {
                *(float2*)(out + (size_t)gm * E_ + gn)       = make_float2(x0, x1);
                *(float2*)(out + (size_t)(gm + 8) * E_ + gn) = make_float2(x2, x3);
            } else {
                uint32_t h0, l0, h1, l1, h2, l2, h3, l3;
                split2(x0, h0, l0); split2(x1, h1, l1);
                split2(x2, h2, l2); split2(x3, h3, l3);
                *(uint32_t*)(outh + (size_t)gm * E_ + gn)       = h0 | (h1 << 16);
                *(uint32_t*)(outl + (size_t)gm * E_ + gn)       = l0 | (l1 << 16);
                *(uint32_t*)(outh + (size_t)(gm + 8) * E_ + gn) = h2 | (h3 << 16);
                *(uint32_t*)(outl + (size_t)(gm + 8) * E_ + gn) = l2 | (l3 << 16);
            }
        }
    }
}

// ---- pre-split A path (O projection) --------------------------------------
__device__ __forceinline__ void gemm_issue_stage(
    uint32_t sb, int s, int m0, int n0, int tid,
    const __nv_bfloat16* Ah, const __nv_bfloat16* Al,
    const __nv_bfloat16* Wh, const __nv_bfloat16* Wl)
{
    const uint32_t base = sb + (uint32_t)(s & 1) * STAGE_B;
    const int k0 = s * KCH;
#pragma unroll
    for (int q = 0; q < 2; q++) {
        const int id  = tid * 2 + q;
        const int row = id >> 2;
        const int c   = id & 3;
        const uint32_t d = base + swz(row, c);
        const size_t ga = (size_t)(m0 + row) * E_ + k0 + c * 8;
        const size_t gw = (size_t)(n0 + row) * E_ + k0 + c * 8;
        cp16(d,              Ah + ga);
        cp16(d + TILE_B,     Al + ga);
        cp16(d + 2 * TILE_B, Wh + gw);
        cp16(d + 3 * TILE_B, Wl + gw);
    }
    asm volatile("cp.async.commit_group;" ::: "memory");
}

__global__ __launch_bounds__(256) void gemm_mma_single(
    const __nv_bfloat16* __restrict__ Ah, const __nv_bfloat16* __restrict__ Al,
    const __nv_bfloat16* __restrict__ Wh, const __nv_bfloat16* __restrict__ Wl,
    const float* __restrict__ bias, float* __restrict__ out)
{
    extern __shared__ char gsm[];
    const uint32_t sb = smem_to_u32(gsm);
    const int tid  = threadIdx.x;
    const int lane = tid & 31;
    const int wid  = tid >> 5;
    const int wm   = wid & 1;
    const int wn   = wid >> 1;
    const int m0 = blockIdx.x * GM;
    const int n0 = blockIdx.y * GN;

    Frag F;
#pragma unroll
    for (int a = 0; a < 4; a++)
#pragma unroll
        for (int b = 0; b < 4; b++)
#pragma unroll
            for (int c = 0; c < 4; c++) F.acc[a][b][c] = 0.f;

    gemm_issue_stage(sb, 0, m0, n0, tid, Ah, Al, Wh, Wl);
    gemm_issue_stage(sb, 1, m0, n0, tid, Ah, Al, Wh, Wl);

    for (int s = 0; s < NST; s++) {
        if (s < NST - 1) asm volatile("cp.async.wait_group 1;" ::: "memory");
        else             asm volatile("cp.async.wait_group 0;" ::: "memory");
        __syncthreads();
        const uint32_t base = sb + (uint32_t)(s & 1) * STAGE_B;
        gemm_stage_math(F, base, base + TILE_B,
                        base + 2 * TILE_B, base + 3 * TILE_B, lane, wm, wn);
        __syncthreads();
        if (s + 2 < NST)
            gemm_issue_stage(sb, s + 2, m0, n0, tid, Ah, Al, Wh, Wl);
    }
    gemm_epilogue(F, bias, out, nullptr, nullptr, 0, m0, n0, lane, wm, wn);
}

// ---- fp32-A path (QKV projections, in-kernel split) ----------------------
__device__ __forceinline__ void gemm_issue_stage_f32(
    uint32_t sb, int s, int m0, int n0, int tid,
    const float* A, const __nv_bfloat16* Wh, const __nv_bfloat16* Wl)
{
    const uint32_t base = sb + (uint32_t)(s & 1) * STAGE_F;
    const int k0 = s * KCH;
    // fp32 A tile: 128 rows x 8 16B-chunks
#pragma unroll
    for (int q = 0; q < 4; q++) {
        const int id  = tid + q * 256;     // 0..1023
        const int row = id >> 3, c = id & 7;
        cp16(base + swz128(row, c),
             A + (size_t)(m0 + row) * E_ + k0 + c * 4);
    }
    // W hi/lo: 128 rows x 4 chunks each
#pragma unroll
    for (int q = 0; q < 2; q++) {
        const int id  = tid * 2 + q;
        const int row = id >> 2, c = id & 3;
        const size_t gw = (size_t)(n0 + row) * E_ + k0 + c * 8;
        cp16(base + AF32_B + 2 * TILE_B + swz(row, c), Wh + gw);
        cp16(base + AF32_B + 3 * TILE_B + swz(row, c), Wl + gw);
    }
    asm volatile("cp.async.commit_group;" ::: "memory");
}

struct GemmF3 {
    const float* A[3];
    const __nv_bfloat16* Wh[3]; const __nv_bfloat16* Wl[3];
    const float* bias[3];
    __nv_bfloat16* outh[3]; __nv_bfloat16* outl[3];
};

__global__ __launch_bounds__(256) void gemm_f32_b3(GemmF3 p) {
    extern __shared__ char gsm[];
    const uint32_t sb = smem_to_u32(gsm);
    const int z = blockIdx.z;
    const float* A = p.A[z];
    const __nv_bfloat16* Wh = p.Wh[z];
    const __nv_bfloat16* Wl = p.Wl[z];
    const int tid  = threadIdx.x;
    const int lane = tid & 31;
    const int wid  = tid >> 5;
    const int wm   = wid & 1;
    const int wn   = wid >> 1;
    const int m0 = blockIdx.x * GM;
    const int n0 = blockIdx.y * GN;

    Frag F;
#pragma unroll
    for (int a = 0; a < 4; a++)
#pragma unroll
        for (int b = 0; b < 4; b++)
#pragma unroll
            for (int c = 0; c < 4; c++) F.acc[a][b][c] = 0.f;

    gemm_issue_stage_f32(sb, 0, m0, n0, tid, A, Wh, Wl);
    gemm_issue_stage_f32(sb, 1, m0, n0, tid, A, Wh, Wl);

    const int crow = tid >> 1, chalf = tid & 1;   // conversion mapping

    for (int s = 0; s < NST; s++) {
        if (s < NST - 1) asm volatile("cp.async.wait_group 1;" ::: "memory");
        else             asm volatile("cp.async.wait_group 0;" ::: "memory");
        __syncthreads();

        char* bufp = gsm + (size_t)(s & 1) * STAGE_F;

        // convert fp32 A tile -> Ah/Al bf16 (16 floats per thread)
        {
            float4 f[4];
#pragma unroll
            for (int cc = 0; cc < 4; cc++)
                f[cc] = *(const float4*)(bufp + swz128(crow, chalf * 4 + cc));
            const float* fv = &f[0].x;
#pragma unroll
            for (int pp = 0; pp < 2; pp++) {
                uint32_t ph[4], pl[4];
#pragma unroll
                for (int e = 0; e < 4; e++) {
                    uint32_t h0, l0, h1, l1;
                    split2(fv[pp * 8 + e * 2 + 0], h0, l0);
                    split2(fv[pp * 8 + e * 2 + 1], h1, l1);
                    ph[e] = h0 | (h1 << 16);
                    pl[e] = l0 | (l1 << 16);
                }
                const uint32_t co = swz(crow, chalf * 2 + pp);
                *(uint4*)(bufp + AF32_B + co) =
                    make_uint4(ph[0], ph[1], ph[2], ph[3]);
                *(uint4*)(bufp + AF32_B + TILE_B + co) =
                    make_uint4(pl[0], pl[1], pl[2], pl[3]);
            }
        }
        __syncthreads();

        const uint32_t base = sb + (uint32_t)(s & 1) * STAGE_F;
        gemm_stage_math(F, base + AF32_B, base + AF32_B + TILE_B,
                        base + AF32_B + 2 * TILE_B, base + AF32_B + 3 * TILE_B,
                        lane, wm, wn);
        __syncthreads();
        if (s + 2 < NST)
            gemm_issue_stage_f32(sb, s + 2, m0, n0, tid, A, Wh, Wl);
    }
    gemm_epilogue(F, p.bias[z], nullptr, p.outh[z], p.outl[z], 1,
                  m0, n0, lane, wm, wn);
}

// ============================ sparse attention =============================
#define QT 64
#define SCLD 200
#define ATTN_SMEM (24576 + QT*SCLD*4)   /* 75776 B -> 3 CTAs/SM */

__global__ __launch_bounds__(256) void attn_tiled(
    float* __restrict__ attn_out,
    __nv_bfloat16* __restrict__ ctx_hi, __nv_bfloat16* __restrict__ ctx_lo,
    const __nv_bfloat16* __restrict__ qh, const __nv_bfloat16* __restrict__ ql,
    const __nv_bfloat16* __restrict__ kh, const __nv_bfloat16* __restrict__ kl,
    const __nv_bfloat16* __restrict__ vh, const __nv_bfloat16* __restrict__ vl)
{
    extern __shared__ char smraw[];
    const uint32_t sb = smem_to_u32(smraw);
    float* sc = (float*)(smraw + 24576);

    const int tid  = threadIdx.x;
    const int lane = tid & 31;
    const int wid  = tid >> 5;
    const int wm   = wid & 3;
    const int wn   = wid >> 2;
    const int qt   = blockIdx.x;
    const int h    = blockIdx.y;
    const int z    = blockIdx.z;

    const int q0     = qt * QT;
    const int we     = q0 + QT - 1;
    const int wstart = (q0 >= WINDOW) ? (q0 - WINDOW) : 0;
    const int Ncs    = wstart >> 2;
    const int NU     = Ncs + (we - wstart + 1);
    const int nch    = (NU + 31) >> 5;

    const size_t tokBase = ((size_t)z * S_) * E_ + h * HD_;

    for (int t = tid; t < 512; t += 256) {
        const int r = t >> 3, c = t & 7;
        const size_t g = tokBase + (size_t)(q0 + r) * E_ + c * 8;
        const uint32_t d = sb + swz128(r, c);
        cp16(d, qh + g);
        cp16(d + 8192, ql + g);
    }
    asm volatile("cp.async.commit_group;" ::: "memory");

    const float NEGINF = __int_as_float(0xff800000);
    for (int ch = 0; ch < nch; ch++) {
        const int uc0 = ch << 5;
        for (int t = tid; t < 256; t += 256) {
            const int r = t >> 3, c = t & 7;
            const int u = uc0 + r;
            int j = 0;
            if (u < NU) j = (u < Ncs) ? (u << 2) : (wstart + u - Ncs);
            const size_t g = tokBase + (size_t)j * E_ + c * 8;
            const uint32_t d = sb + 16384 + swz128(r, c);
            cp16(d, kh + g);
            cp16(d + 4096, kl + g);
        }
        asm volatile("cp.async.commit_group;" ::: "memory");
        asm volatile("cp.async.wait_group 0;" ::: "memory");
        __syncthreads();

        float acc[2][4];
#pragma unroll
        for (int a = 0; a < 2; a++)
#pragma unroll
            for (int b = 0; b < 4; b++) acc[a][b] = 0.f;

#pragma unroll
        for (int kk = 0; kk < 4; kk++) {
            uint32_t ah[4], al[4], bh[4], bl[4];
            {
                const int row = wm * 16 + (lane & 15);
                const int c   = kk * 2 + (lane >> 4);
                ldsm4(ah, sb + swz128(row, c));
                ldsm4(al, sb + 8192 + swz128(row, c));
            }
            {
                const int row = wn * 16 + (lane & 7) + ((lane >> 4) & 1) * 8;
                const int c   = kk * 2 + ((lane >> 3) & 1);
                ldsm4(bh, sb + 16384 + swz128(row, c));
                ldsm4(bl, sb + 20480 + swz128(row, c));
            }
#pragma unroll
            for (int nt = 0; nt < 2; nt++) {
                const int o = nt * 2;
                mma16816(acc[nt], ah, bh[o], bh[o + 1]);
                mma16816(acc[nt], ah, bl[o], bl[o + 1]);
                mma16816(acc[nt], al, bh[o], bh[o + 1]);
            }
        }

        const int r0 = wm * 16 + (lane >> 2);
#pragma unroll
        for (int nt = 0; nt < 2; nt++) {
            const int uc = uc0 + wn * 16 + nt * 8 + (lane & 3) * 2;
            if (uc < NU) {
                const int ja = (uc < Ncs) ? (uc << 2) : (wstart + uc - Ncs);
                const int jb = (uc + 1 < Ncs) ? ((uc + 1) << 2)
                                              : (wstart + uc + 1 - Ncs);
#pragma unroll
                for (int h2 = 0; h2 < 2; h2++) {
                    const int row = r0 + h2 * 8;
                    const int i   = q0 + row;
                    const bool oka = (ja <= i) && ((ja >= i - WINDOW) || ((ja & 3) == 0));
                    const bool okb = (jb <= i) && ((jb >= i - WINDOW) || ((jb & 3) == 0));
                    float2 st;
                    st.x = oka ? acc[nt][h2 * 2 + 0] * 0.125f : NEGINF;
                    st.y = okb ? acc[nt][h2 * 2 + 1] * 0.125f : NEGINF;
                    *(float2*)(sc + row * SCLD + uc) = st;
                }
            }
        }
        __syncthreads();
    }

    // ---- softmax (vectorized, NU % 8 == 0) --------------------------------
    {
        const int row = tid >> 2;
        const int ln  = tid & 3;
        float* srow = sc + row * SCLD;
        const int nv = NU >> 2;
        float m = NEGINF;
        for (int q = ln; q < nv; q += 4) {
            const float4 v = ((const float4*)srow)[q];
            m = fmaxf(m, fmaxf(fmaxf(v.x, v.y), fmaxf(v.z, v.w)));
        }
        m = fmaxf(m, __shfl_xor_sync(0xffffffffu, m, 1));
        m = fmaxf(m, __shfl_xor_sync(0xffffffffu, m, 2));
        float sum = 0.f;
        for (int q = ln; q < nv; q += 4) {
            float4 v = ((const float4*)srow)[q];
            v.x = __expf(v.x - m); v.y = __expf(v.y - m);
            v.z = __expf(v.z - m); v.w = __expf(v.w - m);
            ((float4*)srow)[q] = v;
            sum += v.x + v.y + v.z + v.w;
        }
        sum += __shfl_xor_sync(0xffffffffu, sum, 1);
        sum += __shfl_xor_sync(0xffffffffu, sum, 2);
        const float inv = 1.f / sum;
        for (int q = ln; q < nv; q += 4) {
            float4 v = ((const float4*)srow)[q];
            v.x *= inv; v.y *= inv; v.z *= inv; v.w *= inv;
            ((float4*)srow)[q] = v;
        }
    }
    __syncthreads();

    // ---- dense attn write ([B,H,C,S,S]) -----------------------------------
    {
        const int b = z / C_, c = z % C_;
        float* abase = attn_out +
            ((((size_t)(b * H_ + h) * C_ + c) * S_ + q0) * (size_t)S_);
        for (int t = tid; t < QT * (S_ / 4); t += 256) {
            const int r  = t >> 7;
            const int j0 = (t & 127) << 2;
            const float* srow = sc + r * SCLD;
            float4 v = make_float4(0.f, 0.f, 0.f, 0.f);
            if (j0 <= we) {
                if (j0 >= wstart)
                    v = *(const float4*)(srow + Ncs + j0 - wstart);
                else
                    v.x = srow[j0 >> 2];
            }
            *(float4*)(abase + (size_t)r * S_ + j0) = v;
        }
    }

    // ---- context: HMMA bf16x3, 32-u chunks --------------------------------
    float cacc[4][4];
#pragma unroll
    for (int a = 0; a < 4; a++)
#pragma unroll
        for (int b = 0; b < 4; b++) cacc[a][b] = 0.f;

    for (int ch = 0; ch < nch; ch++) {
        const int uc0 = ch << 5;
        __syncthreads();

        for (int t = tid; t < 256; t += 256) {
            const int r = t >> 3, c = t & 7;
            const int u = uc0 + r;
            int j = 0;
            if (u < NU) j = (u < Ncs) ? (u << 2) : (wstart + u - Ncs);
            const size_t g = tokBase + (size_t)j * E_ + c * 8;
            const uint32_t d = sb + 16384 + swz128(r, c);
            cp16(d, vh + g);
            cp16(d + 4096, vl + g);
        }
        asm volatile("cp.async.commit_group;" ::: "memory");

        for (int t = tid; t < 256; t += 256) {
            const int row = t >> 2, cg = t & 3;
            const int u0 = uc0 + cg * 8;
            float4 pa = make_float4(0.f, 0.f, 0.f, 0.f);
            float4 pb = make_float4(0.f, 0.f, 0.f, 0.f);
            if (u0 < NU) {
                pa = *(const float4*)(sc + row * SCLD + u0);
                pb = *(const float4*)(sc + row * SCLD + u0 + 4);
            }
            const float pv[8] = {pa.x, pa.y, pa.z, pa.w, pb.x, pb.y, pb.z, pb.w};
            uint32_t hp[4], lp[4];
#pragma unroll
            for (int pr = 0; pr < 4; pr++) {
                uint32_t h0, l0, h1, l1;
                split2(pv[pr * 2 + 0], h0, l0);
                split2(pv[pr * 2 + 1], h1, l1);
                hp[pr] = h0 | (h1 << 16);
                lp[pr] = l0 | (l1 << 16);
            }
            *(uint4*)(smraw + swz(row, cg))        = make_uint4(hp[0], hp[1], hp[2], hp[3]);
            *(uint4*)(smraw + 8192 + swz(row, cg)) = make_uint4(lp[0], lp[1], lp[2], lp[3]);
        }
        asm volatile("cp.async.wait_group 0;" ::: "memory");
        __syncthreads();

#pragma unroll
        for (int kk = 0; kk < 2; kk++) {
            uint32_t ah[4], al[4], bh[2][4], bl[2][4];
            {
                const int row = wm * 16 + (lane & 15);
                const int c   = kk * 2 + (lane >> 4);
                ldsm4(ah, sb + swz(row, c));
                ldsm4(al, sb + 8192 + swz(row, c));
            }
#pragma unroll
            for (int np = 0; np < 2; np++) {
                const int row = kk * 16 + (lane & 15);
                const int c   = wn * 4 + np * 2 + (lane >> 4);
                ldsm4t(bh[np], sb + 16384 + swz128(row, c));
                ldsm4t(bl[np], sb + 20480 + swz128(row, c));
            }
#pragma unroll
            for (int nt = 0; nt < 4; nt++) {
                const int np = nt >> 1, o = (nt & 1) * 2;
                mma16816(cacc[nt], ah, bh[np][o], bh[np][o + 1]);
                mma16816(cacc[nt], ah, bl[np][o], bl[np][o + 1]);
                mma16816(cacc[nt], al, bh[np][o], bh[np][o + 1]);
            }
        }
    }

    // ---- epilogue: ctx fragments -> bf16 hi/lo ----------------------------
    {
        const int r0 = wm * 16 + (lane >> 2);
#pragma unroll
        for (int nt = 0; nt < 4; nt++) {
            const int d0 = wn * 32 + nt * 8 + (lane & 3) * 2;
#pragma unroll
            for (int h2 = 0; h2 < 2; h2++) {
                const int i = q0 + r0 + h2 * 8;
                const size_t base = tokBase + (size_t)i * E_ + d0;
                uint32_t h0, l0, h1, l1;
                split2(cacc[nt][h2 * 2 + 0], h0, l0);
                split2(cacc[nt][h2 * 2 + 1], h1, l1);
                *(uint32_t*)(ctx_hi + base) = h0 | (h1 << 16);
                *(uint32_t*)(ctx_lo + base) = l0 | (l1 << 16);
            }
        }
    }
}

// ===========================================================================
extern "C" void kernel_launch(void* const* d_in, const int* in_sizes, int n_in,
                              void* d_out, int out_size)
{
    const float* query = (const float*)d_in[0];
    const float* key_  = (const float*)d_in[1];
    const float* value = (const float*)d_in[2];
    const float* Wq = (const float*)d_in[3];
    const float* bq = (const float*)d_in[4];
    const float* Wk = (const float*)d_in[5];
    const float* bk = (const float*)d_in[6];
    const float* Wv = (const float*)d_in[7];
    const float* bv = (const float*)d_in[8];
    const float* Wo = (const float*)d_in[9];
    const float* bo = (const float*)d_in[10];

    float* out  = (float*)d_out;
    float* attn = out + (size_t)NTOK * E_;

    __nv_bfloat16 *inh, *inl, *Wh4, *Wl4, *qh, *ql, *kh, *kl, *vh, *vl;
    cudaGetSymbolAddress((void**)&inh, g_inh);
    cudaGetSymbolAddress((void**)&inl, g_inl);
    cudaGetSymbolAddress((void**)&Wh4, g_Wh4);
    cudaGetSymbolAddress((void**)&Wl4, g_Wl4);
    cudaGetSymbolAddress((void**)&qh, g_qh);
    cudaGetSymbolAddress((void**)&ql, g_ql);
    cudaGetSymbolAddress((void**)&kh, g_kh);
    cudaGetSymbolAddress((void**)&kl, g_kl);
    cudaGetSymbolAddress((void**)&vh, g_vh);
    cudaGetSymbolAddress((void**)&vl, g_vl);

    cudaFuncSetAttribute(attn_tiled,
        cudaFuncAttributeMaxDynamicSharedMemorySize, ATTN_SMEM);
    cudaFuncSetAttribute(gemm_f32_b3,
        cudaFuncAttributeMaxDynamicSharedMemorySize, GSMEM_F);
    cudaFuncSetAttribute(gemm_mma_single,
        cudaFuncAttributeMaxDynamicSharedMemorySize, GSMEM);

    const size_t WE = (size_t)E_ * E_;
    const int NW4 = E_ * E_ / 4;

    // 1. weight splits (one small launch)
    SplitW4 sw;
    sw.src[0] = (const float4*)Wq; sw.src[1] = (const float4*)Wk;
    sw.src[2] = (const float4*)Wv; sw.src[3] = (const float4*)Wo;
    for (int z = 0; z < 4; z++) {
        sw.hi[z] = (uint2*)(Wh4 + z * WE);
        sw.lo[z] = (uint2*)(Wl4 + z * WE);
    }
    split_w4<<<dim3(NW4 / 512, 1, 4), 256>>>(sw);

    // 2. Q/K/V projections straight from fp32 inputs (in-kernel split)
    GemmF3 gf;
    gf.A[0] = query; gf.A[1] = key_; gf.A[2] = value;
    __nv_bfloat16* oh[3] = {qh, kh, vh};
    __nv_bfloat16* ol[3] = {ql, kl, vl};
    const float* bs[3] = {bq, bk, bv};
    for (int z = 0; z < 3; z++) {
        gf.Wh[z] = Wh4 + z * WE;  gf.Wl[z] = Wl4 + z * WE;
        gf.bias[z] = bs[z];
        gf.outh[z] = oh[z];  gf.outl[z] = ol[z];
    }
    gemm_f32_b3<<<dim3(NTOK / GM, E_ / GN, 3), 256, GSMEM_F>>>(gf);

    // 3. attention (ctx hi/lo into g_inh/g_inl)
    dim3 agrid(S_ / QT, H_, B_ * C_);
    attn_tiled<<<agrid, 256, ATTN_SMEM>>>(attn, inh, inl,
                                          qh, ql, kh, kl, vh, vl);

    // 4. output projection (pre-split A from attn)
    gemm_mma_single<<<dim3(NTOK / GM, E_ / GN), 256, GSMEM>>>(
        inh, inl, Wh4 + 3 * WE, Wl4 + 3 * WE, bo, out);
}

// round 15
// speedup vs baseline: 1.2231x; 1.0058x over previous
#include <cuda_runtime.h>
#include <cuda_bf16.h>
#include <math.h>
#include <stdint.h>

#define B_ 4
#define C_ 8
#define S_ 512
#define E_ 512
#define H_ 8
#define HD_ 64
#define WINDOW 32
#define NTOK (B_*C_*S_)   /* 16384 */

// ctx split (written by attn, read by O-projection)
static __device__ __nv_bfloat16 g_inh[(size_t)NTOK * E_];
static __device__ __nv_bfloat16 g_inl[(size_t)NTOK * E_];
// weight splits: 4 regions (Wq,Wk,Wv,Wo)
static __device__ __nv_bfloat16 g_Wh4[(size_t)4 * E_ * E_];
static __device__ __nv_bfloat16 g_Wl4[(size_t)4 * E_ * E_];
// projected q/k/v hi/lo
static __device__ __nv_bfloat16 g_qh[(size_t)NTOK * E_];
static __device__ __nv_bfloat16 g_ql[(size_t)NTOK * E_];
static __device__ __nv_bfloat16 g_kh[(size_t)NTOK * E_];
static __device__ __nv_bfloat16 g_kl[(size_t)NTOK * E_];
static __device__ __nv_bfloat16 g_vh[(size_t)NTOK * E_];
static __device__ __nv_bfloat16 g_vl[(size_t)NTOK * E_];

// ============================ helpers ======================================
__device__ __forceinline__ uint32_t smem_to_u32(const void* p) {
    uint32_t a;
    asm("{ .reg .u64 t; cvta.to.shared.u64 t, %1; cvt.u32.u64 %0, t; }"
        : "=r"(a) : "l"(p));
    return a;
}
__device__ __forceinline__ void cp16(uint32_t dst, const void* src) {
    asm volatile("cp.async.cg.shared.global [%0], [%1], 16;"
                 :: "r"(dst), "l"(src) : "memory");
}
__device__ __forceinline__ void ldsm4(uint32_t* r, uint32_t addr) {
    asm volatile("ldmatrix.sync.aligned.m8n8.x4.shared.b16 {%0,%1,%2,%3}, [%4];"
                 : "=r"(r[0]), "=r"(r[1]), "=r"(r[2]), "=r"(r[3]) : "r"(addr));
}
__device__ __forceinline__ void ldsm4t(uint32_t* r, uint32_t addr) {
    asm volatile("ldmatrix.sync.aligned.m8n8.x4.trans.shared.b16 {%0,%1,%2,%3}, [%4];"
                 : "=r"(r[0]), "=r"(r[1]), "=r"(r[2]), "=r"(r[3]) : "r"(addr));
}
__device__ __forceinline__ void mma16816(float* d, const uint32_t* a,
                                         uint32_t b0, uint32_t b1) {
    asm volatile("mma.sync.aligned.m16n8k16.row.col.f32.bf16.bf16.f32 "
                 "{%0,%1,%2,%3}, {%4,%5,%6,%7}, {%8,%9}, {%0,%1,%2,%3};"
                 : "+f"(d[0]), "+f"(d[1]), "+f"(d[2]), "+f"(d[3])
                 : "r"(a[0]), "r"(a[1]), "r"(a[2]), "r"(a[3]), "r"(b0), "r"(b1));
}
__device__ __forceinline__ uint32_t swz(int row, int c) {
    return (uint32_t)(row * 64 + ((c ^ ((row >> 1) & 3)) << 4));
}
__device__ __forceinline__ uint32_t swz128(int row, int c) {
    return (uint32_t)(row * 128 + ((c ^ (row & 7)) << 4));
}
__device__ __forceinline__ void split2(float x, uint32_t& h, uint32_t& l) {
    __nv_bfloat16 hb = __float2bfloat16(x);
    __nv_bfloat16 lb = __float2bfloat16(x - __bfloat162float(hb));
    h = (uint32_t)__bfloat16_as_ushort(hb);
    l = (uint32_t)__bfloat16_as_ushort(lb);
}

// ============================ weight split kernel ==========================
struct SplitW4 { const float4* src[4]; uint2* hi[4]; uint2* lo[4]; };

__device__ __forceinline__ void split_one(const float4* src, uint2* hi,
                                          uint2* lo, int i) {
    float4 v = src[i];
    uint32_t h[4], l[4];
    split2(v.x, h[0], l[0]); split2(v.y, h[1], l[1]);
    split2(v.z, h[2], l[2]); split2(v.w, h[3], l[3]);
    uint2 ph, pl;
    ph.x = h[0] | (h[1] << 16); ph.y = h[2] | (h[3] << 16);
    pl.x = l[0] | (l[1] << 16); pl.y = l[2] | (l[3] << 16);
    hi[i] = ph; lo[i] = pl;
}
__global__ __launch_bounds__(256) void split_w4(SplitW4 p) {
    const int z = blockIdx.z;
    const int i = blockIdx.x * 512 + threadIdx.x;
    split_one(p.src[z], p.hi[z], p.lo[z], i);
    split_one(p.src[z], p.hi[z], p.lo[z], i + 256);
}

// ============================ HMMA GEMM ====================================
#define GM 128
#define GN 128
#define KCH 32
#define NST (E_/KCH)             /* 16 */
#define TILE_B (128*64)          /* 8192  */
#define STAGE_B (4*TILE_B)       /* 32768 (pre-split A path) */
#define GSMEM (2*STAGE_B)        /* 65536 */
#define AF32_B 16384             /* fp32 A tile: 128 x 32 x 4B */
#define STAGE_F (AF32_B + 4*TILE_B)  /* 49152 (fp32-A path) */
#define GSMEM_F (2*STAGE_F)      /* 98304 */

struct Frag { float acc[4][4][4]; };

__device__ __forceinline__ void gemm_stage_math(
    Frag& F, uint32_t ahB, uint32_t alB, uint32_t whB, uint32_t wlB,
    int lane, int wm, int wn)
{
#pragma unroll
    for (int ks = 0; ks < 2; ks++) {
        uint32_t af[4][4], whf[2][4], wlf[2][4];
#pragma unroll
        for (int mt = 0; mt < 4; mt++) {
            const int row = wm * 64 + mt * 16 + (lane & 15);
            const int c   = ks * 2 + (lane >> 4);
            ldsm4(af[mt], ahB + swz(row, c));
        }
#pragma unroll
        for (int np = 0; np < 2; np++) {
            const int row = wn * 32 + np * 16 + (lane & 7) + ((lane >> 4) & 1) * 8;
            const int c   = ks * 2 + ((lane >> 3) & 1);
            ldsm4(whf[np], whB + swz(row, c));
            ldsm4(wlf[np], wlB + swz(row, c));
        }
#pragma unroll
        for (int mt = 0; mt < 4; mt++)
#pragma unroll
            for (int nt = 0; nt < 4; nt++) {
                const int np = nt >> 1, o = (nt & 1) * 2;
                mma16816(F.acc[mt][nt], af[mt], whf[np][o], whf[np][o + 1]);
                mma16816(F.acc[mt][nt], af[mt], wlf[np][o], wlf[np][o + 1]);
            }
#pragma unroll
        for (int mt = 0; mt < 4; mt++) {
            const int row = wm * 64 + mt * 16 + (lane & 15);
            const int c   = ks * 2 + (lane >> 4);
            ldsm4(af[mt], alB + swz(row, c));
        }
#pragma unroll
        for (int mt = 0; mt < 4; mt++)
#pragma unroll
            for (int nt = 0; nt < 4; nt++) {
                const int np = nt >> 1, o = (nt & 1) * 2;
                mma16816(F.acc[mt][nt], af[mt], whf[np][o], whf[np][o + 1]);
            }
    }
}

__device__ __forceinline__ void gemm_epilogue(
    Frag& F, const float* bias, float* out,
    __nv_bfloat16* outh, __nv_bfloat16* outl, int mode,
    int m0, int n0, int lane, int wm, int wn)
{
#pragma unroll
    for (int nt = 0; nt < 4; nt++) {
        const int gn = n0 + wn * 32 + nt * 8 + (lane & 3) * 2;
        const float2 bv = *(const float2*)(bias + gn);
#pragma unroll
        for (int mt = 0; mt < 4; mt++) {
            const int gm = m0 + wm * 64 + mt * 16 + (lane >> 2);
            float x0 = F.acc[mt][nt][0] + bv.x, x1 = F.acc[mt][nt][1] + bv.y;
            float x2 = F.acc[mt][nt][2] + bv.x, x3 = F.acc[mt][nt][3] + bv.y;
            if (mode == 0) {
                *(float2*)(out + (size_t)gm * E_ + gn)       = make_float2(x0, x1);
                *(float2*)(out + (size_t)(gm + 8) * E_ + gn) = make_float2(x2, x3);
            } else {
                uint32_t h0, l0, h1, l1, h2, l2, h3, l3;
                split2(x0, h0, l0); split2(x1, h1, l1);
                split2(x2, h2, l2); split2(x3, h3, l3);
                *(uint32_t*)(outh + (size_t)gm * E_ + gn)       = h0 | (h1 << 16);
                *(uint32_t*)(outl + (size_t)gm * E_ + gn)       = l0 | (l1 << 16);
                *(uint32_t*)(outh + (size_t)(gm + 8) * E_ + gn) = h2 | (h3 << 16);
                *(uint32_t*)(outl + (size_t)(gm + 8) * E_ + gn) = l2 | (l3 << 16);
            }
        }
    }
}

// ---- pre-split A path (O projection) --------------------------------------
__device__ __forceinline__ void gemm_issue_stage(
    uint32_t sb, int s, int m0, int n0, int tid,
    const __nv_bfloat16* Ah, const __nv_bfloat16* Al,
    const __nv_bfloat16* Wh, const __nv_bfloat16* Wl)
{
    const uint32_t base = sb + (uint32_t)(s & 1) * STAGE_B;
    const int k0 = s * KCH;
#pragma unroll
    for (int q = 0; q < 2; q++) {
        const int id  = tid * 2 + q;
        const int row = id >> 2;
        const int c   = id & 3;
        const uint32_t d = base + swz(row, c);
        const size_t ga = (size_t)(m0 + row) * E_ + k0 + c * 8;
        const size_t gw = (size_t)(n0 + row) * E_ + k0 + c * 8;
        cp16(d,              Ah + ga);
        cp16(d + TILE_B,     Al + ga);
        cp16(d + 2 * TILE_B, Wh + gw);
        cp16(d + 3 * TILE_B, Wl + gw);
    }
    asm volatile("cp.async.commit_group;" ::: "memory");
}

__global__ __launch_bounds__(256) void gemm_mma_single(
    const __nv_bfloat16* __restrict__ Ah, const __nv_bfloat16* __restrict__ Al,
    const __nv_bfloat16* __restrict__ Wh, const __nv_bfloat16* __restrict__ Wl,
    const float* __restrict__ bias, float* __restrict__ out)
{
    extern __shared__ char gsm[];
    const uint32_t sb = smem_to_u32(gsm);
    const int tid  = threadIdx.x;
    const int lane = tid & 31;
    const int wid  = tid >> 5;
    const int wm   = wid & 1;
    const int wn   = wid >> 1;
    const int m0 = blockIdx.x * GM;
    const int n0 = blockIdx.y * GN;

    Frag F;
#pragma unroll
    for (int a = 0; a < 4; a++)
#pragma unroll
        for (int b = 0; b < 4; b++)
#pragma unroll
            for (int c = 0; c < 4; c++) F.acc[a][b][c] = 0.f;

    gemm_issue_stage(sb, 0, m0, n0, tid, Ah, Al, Wh, Wl);
    gemm_issue_stage(sb, 1, m0, n0, tid, Ah, Al, Wh, Wl);

    for (int s = 0; s < NST; s++) {
        if (s < NST - 1) asm volatile("cp.async.wait_group 1;" ::: "memory");
        else             asm volatile("cp.async.wait_group 0;" ::: "memory");
        __syncthreads();
        const uint32_t base = sb + (uint32_t)(s & 1) * STAGE_B;
        gemm_stage_math(F, base, base + TILE_B,
                        base + 2 * TILE_B, base + 3 * TILE_B, lane, wm, wn);
        __syncthreads();
        if (s + 2 < NST)
            gemm_issue_stage(sb, s + 2, m0, n0, tid, Ah, Al, Wh, Wl);
    }
    gemm_epilogue(F, bias, out, nullptr, nullptr, 0, m0, n0, lane, wm, wn);
}

// ---- fp32-A path (QKV projections, in-kernel split) ----------------------
__device__ __forceinline__ void gemm_issue_stage_f32(
    uint32_t sb, int s, int m0, int n0, int tid,
    const float* A, const __nv_bfloat16* Wh, const __nv_bfloat16* Wl)
{
    const uint32_t base = sb + (uint32_t)(s & 1) * STAGE_F;
    const int k0 = s * KCH;
#pragma unroll
    for (int q = 0; q < 4; q++) {
        const int id  = tid + q * 256;
        const int row = id >> 3, c = id & 7;
        cp16(base + swz128(row, c),
             A + (size_t)(m0 + row) * E_ + k0 + c * 4);
    }
#pragma unroll
    for (int q = 0; q < 2; q++) {
        const int id  = tid * 2 + q;
        const int row = id >> 2, c = id & 3;
        const size_t gw = (size_t)(n0 + row) * E_ + k0 + c * 8;
        cp16(base + AF32_B + 2 * TILE_B + swz(row, c), Wh + gw);
        cp16(base + AF32_B + 3 * TILE_B + swz(row, c), Wl + gw);
    }
    asm volatile("cp.async.commit_group;" ::: "memory");
}

struct GemmF3 {
    const float* A[3];
    const __nv_bfloat16* Wh[3]; const __nv_bfloat16* Wl[3];
    const float* bias[3];
    __nv_bfloat16* outh[3]; __nv_bfloat16* outl[3];
};

__global__ __launch_bounds__(256) void gemm_f32_b3(GemmF3 p) {
    extern __shared__ char gsm[];
    const uint32_t sb = smem_to_u32(gsm);
    const int z = blockIdx.z;
    const float* A = p.A[z];
    const __nv_bfloat16* Wh = p.Wh[z];
    const __nv_bfloat16* Wl = p.Wl[z];
    const int tid  = threadIdx.x;
    const int lane = tid & 31;
    const int wid  = tid >> 5;
    const int wm   = wid & 1;
    const int wn   = wid >> 1;
    const int m0 = blockIdx.x * GM;
    const int n0 = blockIdx.y * GN;

    Frag F;
#pragma unroll
    for (int a = 0; a < 4; a++)
#pragma unroll
        for (int b = 0; b < 4; b++)
#pragma unroll
            for (int c = 0; c < 4; c++) F.acc[a][b][c] = 0.f;

    gemm_issue_stage_f32(sb, 0, m0, n0, tid, A, Wh, Wl);
    gemm_issue_stage_f32(sb, 1, m0, n0, tid, A, Wh, Wl);

    const int crow = tid >> 1, chalf = tid & 1;

    for (int s = 0; s < NST; s++) {
        if (s < NST - 1) asm volatile("cp.async.wait_group 1;" ::: "memory");
        else             asm volatile("cp.async.wait_group 0;" ::: "memory");
        __syncthreads();

        char* bufp = gsm + (size_t)(s & 1) * STAGE_F;
        {
            float4 f[4];
#pragma unroll
            for (int cc = 0; cc < 4; cc++)
                f[cc] = *(const float4*)(bufp + swz128(crow, chalf * 4 + cc));
            const float* fv = &f[0].x;
#pragma unroll
            for (int pp = 0; pp < 2; pp++) {
                uint32_t ph[4], pl[4];
#pragma unroll
                for (int e = 0; e < 4; e++) {
                    uint32_t h0, l0, h1, l1;
                    split2(fv[pp * 8 + e * 2 + 0], h0, l0);
                    split2(fv[pp * 8 + e * 2 + 1], h1, l1);
                    ph[e] = h0 | (h1 << 16);
                    pl[e] = l0 | (l1 << 16);
                }
                const uint32_t co = swz(crow, chalf * 2 + pp);
                *(uint4*)(bufp + AF32_B + co) =
                    make_uint4(ph[0], ph[1], ph[2], ph[3]);
                *(uint4*)(bufp + AF32_B + TILE_B + co) =
                    make_uint4(pl[0], pl[1], pl[2], pl[3]);
            }
        }
        __syncthreads();

        const uint32_t base = sb + (uint32_t)(s & 1) * STAGE_F;
        gemm_stage_math(F, base + AF32_B, base + AF32_B + TILE_B,
                        base + AF32_B + 2 * TILE_B, base + AF32_B + 3 * TILE_B,
                        lane, wm, wn);
        __syncthreads();
        if (s + 2 < NST)
            gemm_issue_stage_f32(sb, s + 2, m0, n0, tid, A, Wh, Wl);
    }
    gemm_epilogue(F, p.bias[z], nullptr, p.outh[z], p.outl[z], 1,
                  m0, n0, lane, wm, wn);
}

// ============================ sparse attention =============================
// smem (bytes):
//   [0, 8192)      Qh (score)     / Ph [0,4096) (ctx)
//   [8192, 16384)  Ql (score)     / Pl [8192,12288) (ctx)
//   [16384, 24576) K/V buf0 (hi at +0, lo at +4096)
//   [24576, 32768) K/V buf1
//   [32768, ...)   sc fp32 [64][SCLD]
#define QT 64
#define SCLD 200
#define ATTN_SMEM (32768 + QT*SCLD*4)   /* 83968 B -> 2 CTAs/SM */

__global__ __launch_bounds__(256) void attn_tiled(
    float* __restrict__ attn_out,
    __nv_bfloat16* __restrict__ ctx_hi, __nv_bfloat16* __restrict__ ctx_lo,
    const __nv_bfloat16* __restrict__ qh, const __nv_bfloat16* __restrict__ ql,
    const __nv_bfloat16* __restrict__ kh, const __nv_bfloat16* __restrict__ kl,
    const __nv_bfloat16* __restrict__ vh, const __nv_bfloat16* __restrict__ vl)
{
    extern __shared__ char smraw[];
    const uint32_t sb = smem_to_u32(smraw);
    float* sc = (float*)(smraw + 32768);

    const int tid  = threadIdx.x;
    const int lane = tid & 31;
    const int wid  = tid >> 5;
    const int wm   = wid & 3;
    const int wn   = wid >> 2;
    const int qt   = blockIdx.x;
    const int h    = blockIdx.y;
    const int z    = blockIdx.z;

    const int q0     = qt * QT;
    const int we     = q0 + QT - 1;
    const int wstart = (q0 >= WINDOW) ? (q0 - WINDOW) : 0;
    const int Ncs    = wstart >> 2;
    const int NU     = Ncs + (we - wstart + 1);
    const int nch    = (NU + 31) >> 5;

    const size_t tokBase = ((size_t)z * S_) * E_ + h * HD_;

    // ---- Q tiles (group 0) -------------------------------------------------
    for (int t = tid; t < 512; t += 256) {
        const int r = t >> 3, c = t & 7;
        const size_t g = tokBase + (size_t)(q0 + r) * E_ + c * 8;
        const uint32_t d = sb + swz128(r, c);
        cp16(d, qh + g);
        cp16(d + 8192, ql + g);
    }
    asm volatile("cp.async.commit_group;" ::: "memory");

    // chunk loader: K/V rows for chunk ch into buf (ch&1)
    auto issue_kv = [&](const __nv_bfloat16* xh, const __nv_bfloat16* xl,
                        int ch) {
        const int uc0 = ch << 5;
        const uint32_t buf = sb + 16384 + (uint32_t)(ch & 1) * 8192;
        for (int t = tid; t < 256; t += 256) {
            const int r = t >> 3, c = t & 7;
            const int u = uc0 + r;
            int j = 0;      // u >= NU: garbage row (masked / P=0)
            if (u < NU) j = (u < Ncs) ? (u << 2) : (wstart + u - Ncs);
            const size_t g = tokBase + (size_t)j * E_ + c * 8;
            cp16(buf + swz128(r, c), xh + g);
            cp16(buf + 4096 + swz128(r, c), xl + g);
        }
        asm volatile("cp.async.commit_group;" ::: "memory");
    };

    // ---- scores: HMMA bf16x3, 32-u chunks, double-buffered K ---------------
    const float NEGINF = __int_as_float(0xff800000);
    issue_kv(kh, kl, 0);
    for (int ch = 0; ch < nch; ch++) {
        if (ch + 1 < nch) {
            issue_kv(kh, kl, ch + 1);
            asm volatile("cp.async.wait_group 1;" ::: "memory");
        } else {
            asm volatile("cp.async.wait_group 0;" ::: "memory");
        }
        __syncthreads();

        const int uc0 = ch << 5;
        const uint32_t kB = sb + 16384 + (uint32_t)(ch & 1) * 8192;

        float acc[2][4];
#pragma unroll
        for (int a = 0; a < 2; a++)
#pragma unroll
            for (int b = 0; b < 4; b++) acc[a][b] = 0.f;

#pragma unroll
        for (int kk = 0; kk < 4; kk++) {
            uint32_t ah[4], al[4], bh[4], bl[4];
            {
                const int row = wm * 16 + (lane & 15);
                const int c   = kk * 2 + (lane >> 4);
                ldsm4(ah, sb + swz128(row, c));
                ldsm4(al, sb + 8192 + swz128(row, c));
            }
            {
                const int row = wn * 16 + (lane & 7) + ((lane >> 4) & 1) * 8;
                const int c   = kk * 2 + ((lane >> 3) & 1);
                ldsm4(bh, kB + swz128(row, c));
                ldsm4(bl, kB + 4096 + swz128(row, c));
            }
#pragma unroll
            for (int nt = 0; nt < 2; nt++) {
                const int o = nt * 2;
                mma16816(acc[nt], ah, bh[o], bh[o + 1]);
                mma16816(acc[nt], ah, bl[o], bl[o + 1]);
                mma16816(acc[nt], al, bh[o], bh[o + 1]);
            }
        }

        const int r0 = wm * 16 + (lane >> 2);
#pragma unroll
        for (int nt = 0; nt < 2; nt++) {
            const int uc = uc0 + wn * 16 + nt * 8 + (lane & 3) * 2;
            if (uc < NU) {
                const int ja = (uc < Ncs) ? (uc << 2) : (wstart + uc - Ncs);
                const int jb = (uc + 1 < Ncs) ? ((uc + 1) << 2)
                                              : (wstart + uc + 1 - Ncs);
#pragma unroll
                for (int h2 = 0; h2 < 2; h2++) {
                    const int row = r0 + h2 * 8;
                    const int i   = q0 + row;
                    const bool oka = (ja <= i) && ((ja >= i - WINDOW) || ((ja & 3) == 0));
                    const bool okb = (jb <= i) && ((jb >= i - WINDOW) || ((jb & 3) == 0));
                    float2 st;
                    st.x = oka ? acc[nt][h2 * 2 + 0] * 0.125f : NEGINF;
                    st.y = okb ? acc[nt][h2 * 2 + 1] * 0.125f : NEGINF;
                    *(float2*)(sc + row * SCLD + uc) = st;
                }
            }
        }
        __syncthreads();   // buf (ch&1) free for issue of ch+2
    }

    // ---- softmax (vectorized, NU % 8 == 0) --------------------------------
    {
        const int row = tid >> 2;
        const int ln  = tid & 3;
        float* srow = sc + row * SCLD;
        const int nv = NU >> 2;
        float m = NEGINF;
        for (int q = ln; q < nv; q += 4) {
            const float4 v = ((const float4*)srow)[q];
            m = fmaxf(m, fmaxf(fmaxf(v.x, v.y), fmaxf(v.z, v.w)));
        }
        m = fmaxf(m, __shfl_xor_sync(0xffffffffu, m, 1));
        m = fmaxf(m, __shfl_xor_sync(0xffffffffu, m, 2));
        float sum = 0.f;
        for (int q = ln; q < nv; q += 4) {
            float4 v = ((const float4*)srow)[q];
            v.x = __expf(v.x - m); v.y = __expf(v.y - m);
            v.z = __expf(v.z - m); v.w = __expf(v.w - m);
            ((float4*)srow)[q] = v;
            sum += v.x + v.y + v.z + v.w;
        }
        sum += __shfl_xor_sync(0xffffffffu, sum, 1);
        sum += __shfl_xor_sync(0xffffffffu, sum, 2);
        const float inv = 1.f / sum;
        for (int q = ln; q < nv; q += 4) {
            float4 v = ((const float4*)srow)[q];
            v.x *= inv; v.y *= inv; v.z *= inv; v.w *= inv;
            ((float4*)srow)[q] = v;
        }
    }
    __syncthreads();

    // pre-issue V chunk 0: latency hides under the dense attn write
    issue_kv(vh, vl, 0);

    // ---- dense attn write ([B,H,C,S,S]) -----------------------------------
    {
        const int b = z / C_, c = z % C_;
        float* abase = attn_out +
            ((((size_t)(b * H_ + h) * C_ + c) * S_ + q0) * (size_t)S_);
        for (int t = tid; t < QT * (S_ / 4); t += 256) {
            const int r  = t >> 7;
            const int j0 = (t & 127) << 2;
            const float* srow = sc + r * SCLD;
            float4 v = make_float4(0.f, 0.f, 0.f, 0.f);
            if (j0 <= we) {
                if (j0 >= wstart)
                    v = *(const float4*)(srow + Ncs + j0 - wstart);
                else
                    v.x = srow[j0 >> 2];
            }
            *(float4*)(abase + (size_t)r * S_ + j0) = v;
        }
    }

    // ---- context: HMMA bf16x3, 32-u chunks, double-buffered V --------------
    float cacc[4][4];
#pragma unroll
    for (int a = 0; a < 4; a++)
#pragma unroll
        for (int b = 0; b < 4; b++) cacc[a][b] = 0.f;

    for (int ch = 0; ch < nch; ch++) {
        const int uc0 = ch << 5;
        if (ch + 1 < nch) issue_kv(vh, vl, ch + 1);

        // P chunk fp32 -> Ph/Pl bf16 (region A; previous math done via
        // trailing sync, reads sc only)
        for (int t = tid; t < 256; t += 256) {
            const int row = t >> 2, cg = t & 3;
            const int u0 = uc0 + cg * 8;
            float4 pa = make_float4(0.f, 0.f, 0.f, 0.f);
            float4 pb = make_float4(0.f, 0.f, 0.f, 0.f);
            if (u0 < NU) {
                pa = *(const float4*)(sc + row * SCLD + u0);
                pb = *(const float4*)(sc + row * SCLD + u0 + 4);
            }
            const float pv[8] = {pa.x, pa.y, pa.z, pa.w, pb.x, pb.y, pb.z, pb.w};
            uint32_t hp[4], lp[4];
#pragma unroll
            for (int pr = 0; pr < 4; pr++) {
                uint32_t h0, l0, h1, l1;
                split2(pv[pr * 2 + 0], h0, l0);
                split2(pv[pr * 2 + 1], h1, l1);
                hp[pr] = h0 | (h1 << 16);
                lp[pr] = l0 | (l1 << 16);
            }
            *(uint4*)(smraw + swz(row, cg))        = make_uint4(hp[0], hp[1], hp[2], hp[3]);
            *(uint4*)(smraw + 8192 + swz(row, cg)) = make_uint4(lp[0], lp[1], lp[2], lp[3]);
        }
        if (ch + 1 < nch)
            asm volatile("cp.async.wait_group 1;" ::: "memory");
        else
            asm volatile("cp.async.wait_group 0;" ::: "memory");
        __syncthreads();

        const uint32_t vB = sb + 16384 + (uint32_t)(ch & 1) * 8192;
#pragma unroll
        for (int kk = 0; kk < 2; kk++) {
            uint32_t ah[4], al[4], bh[2][4], bl[2][4];
            {
                const int row = wm * 16 + (lane & 15);
                const int c   = kk * 2 + (lane >> 4);
                ldsm4(ah, sb + swz(row, c));
                ldsm4(al, sb + 8192 + swz(row, c));
            }
#pragma unroll
            for (int np = 0; np < 2; np++) {
                const int row = kk * 16 + (lane & 15);
                const int c   = wn * 4 + np * 2 + (lane >> 4);
                ldsm4t(bh[np], vB + swz128(row, c));
                ldsm4t(bl[np], vB + 4096 + swz128(row, c));
            }
#pragma unroll
            for (int nt = 0; nt < 4; nt++) {
                const int np = nt >> 1, o = (nt & 1) * 2;
                mma16816(cacc[nt], ah, bh[np][o], bh[np][o + 1]);
                mma16816(cacc[nt], ah, bl[np][o], bl[np][o + 1]);
                mma16816(cacc[nt], al, bh[np][o], bh[np][o + 1]);
            }
        }
        __syncthreads();   // region A + buf (ch&1) free
    }

    // ---- epilogue: ctx fragments -> bf16 hi/lo ----------------------------
    {
        const int r0 = wm * 16 + (lane >> 2);
#pragma unroll
        for (int nt = 0; nt < 4; nt++) {
            const int d0 = wn * 32 + nt * 8 + (lane & 3) * 2;
#pragma unroll
            for (int h2 = 0; h2 < 2; h2++) {
                const int i = q0 + r0 + h2 * 8;
                const size_t base = tokBase + (size_t)i * E_ + d0;
                uint32_t h0, l0, h1, l1;
                split2(cacc[nt][h2 * 2 + 0], h0, l0);
                split2(cacc[nt][h2 * 2 + 1], h1, l1);
                *(uint32_t*)(ctx_hi + base) = h0 | (h1 << 16);
                *(uint32_t*)(ctx_lo + base) = l0 | (l1 << 16);
            }
        }
    }
}

// ===========================================================================
extern "C" void kernel_launch(void* const* d_in, const int* in_sizes, int n_in,
                              void* d_out, int out_size)
{
    const float* query = (const float*)d_in[0];
    const float* key_  = (const float*)d_in[1];
    const float* value = (const float*)d_in[2];
    const float* Wq = (const float*)d_in[3];
    const float* bq = (const float*)d_in[4];
    const float* Wk = (const float*)d_in[5];
    const float* bk = (const float*)d_in[6];
    const float* Wv = (const float*)d_in[7];
    const float* bv = (const float*)d_in[8];
    const float* Wo = (const float*)d_in[9];
    const float* bo = (const float*)d_in[10];

    float* out  = (float*)d_out;
    float* attn = out + (size_t)NTOK * E_;

    __nv_bfloat16 *inh, *inl, *Wh4, *Wl4, *qh, *ql, *kh, *kl, *vh, *vl;
    cudaGetSymbolAddress((void**)&inh, g_inh);
    cudaGetSymbolAddress((void**)&inl, g_inl);
    cudaGetSymbolAddress((void**)&Wh4, g_Wh4);
    cudaGetSymbolAddress((void**)&Wl4, g_Wl4);
    cudaGetSymbolAddress((void**)&qh, g_qh);
    cudaGetSymbolAddress((void**)&ql, g_ql);
    cudaGetSymbolAddress((void**)&kh, g_kh);
    cudaGetSymbolAddress((void**)&kl, g_kl);
    cudaGetSymbolAddress((void**)&vh, g_vh);
    cudaGetSymbolAddress((void**)&vl, g_vl);

    cudaFuncSetAttribute(attn_tiled,
        cudaFuncAttributeMaxDynamicSharedMemorySize, ATTN_SMEM);
    cudaFuncSetAttribute(gemm_f32_b3,
        cudaFuncAttributeMaxDynamicSharedMemorySize, GSMEM_F);
    cudaFuncSetAttribute(gemm_mma_single,
        cudaFuncAttributeMaxDynamicSharedMemorySize, GSMEM);

    const size_t WE = (size_t)E_ * E_;
    const int NW4 = E_ * E_ / 4;

    SplitW4 sw;
    sw.src[0] = (const float4*)Wq; sw.src[1] = (const float4*)Wk;
    sw.src[2] = (const float4*)Wv; sw.src[3] = (const float4*)Wo;
    for (int z = 0; z < 4; z++) {
        sw.hi[z] = (uint2*)(Wh4 + z * WE);
        sw.lo[z] = (uint2*)(Wl4 + z * WE);
    }
    split_w4<<<dim3(NW4 / 512, 1, 4), 256>>>(sw);

    GemmF3 gf;
    gf.A[0] = query; gf.A[1] = key_; gf.A[2] = value;
    __nv_bfloat16* oh[3] = {qh, kh, vh};
    __nv_bfloat16* ol[3] = {ql, kl, vl};
    const float* bs[3] = {bq, bk, bv};
    for (int z = 0; z < 3; z++) {
        gf.Wh[z] = Wh4 + z * WE;  gf.Wl[z] = Wl4 + z * WE;
        gf.bias[z] = bs[z];
        gf.outh[z] = oh[z];  gf.outl[z] = ol[z];
    }
    gemm_f32_b3<<<dim3(NTOK / GM, E_ / GN, 3), 256, GSMEM_F>>>(gf);

    dim3 agrid(S_ / QT, H_, B_ * C_);
    attn_tiled<<<agrid, 256, ATTN_SMEM>>>(attn, inh, inl,
                                          qh, ql, kh, kl, vh, vl);

    gemm_mma_single<<<dim3(NTOK / GM, E_ / GN), 256, GSMEM>>>(
        inh, inl, Wh4 + 3 * WE, Wl4 + 3 * WE, bo, out);
}

// round 16
// speedup vs baseline: 1.2231x; 1.0001x over previous
#include <cuda_runtime.h>
#include <cuda_bf16.h>
#include <math.h>
#include <stdint.h>

#define B_ 4
#define C_ 8
#define S_ 512
#define E_ 512
#define H_ 8
#define HD_ 64
#define WINDOW 32
#define NTOK (B_*C_*S_)   /* 16384 */

static __device__ __nv_bfloat16 g_inh[(size_t)NTOK * E_];
static __device__ __nv_bfloat16 g_inl[(size_t)NTOK * E_];
static __device__ __nv_bfloat16 g_Wh4[(size_t)4 * E_ * E_];
static __device__ __nv_bfloat16 g_Wl4[(size_t)4 * E_ * E_];
static __device__ __nv_bfloat16 g_qh[(size_t)NTOK * E_];
static __device__ __nv_bfloat16 g_ql[(size_t)NTOK * E_];
static __device__ __nv_bfloat16 g_kh[(size_t)NTOK * E_];
static __device__ __nv_bfloat16 g_kl[(size_t)NTOK * E_];
static __device__ __nv_bfloat16 g_vh[(size_t)NTOK * E_];
static __device__ __nv_bfloat16 g_vl[(size_t)NTOK * E_];

// ============================ helpers ======================================
__device__ __forceinline__ uint32_t smem_to_u32(const void* p) {
    uint32_t a;
    asm("{ .reg .u64 t; cvta.to.shared.u64 t, %1; cvt.u32.u64 %0, t; }"
        : "=r"(a) : "l"(p));
    return a;
}
__device__ __forceinline__ void cp16(uint32_t dst, const void* src) {
    asm volatile("cp.async.cg.shared.global [%0], [%1], 16;"
                 :: "r"(dst), "l"(src) : "memory");
}
__device__ __forceinline__ void ldsm4(uint32_t* r, uint32_t addr) {
    asm volatile("ldmatrix.sync.aligned.m8n8.x4.shared.b16 {%0,%1,%2,%3}, [%4];"
                 : "=r"(r[0]), "=r"(r[1]), "=r"(r[2]), "=r"(r[3]) : "r"(addr));
}
__device__ __forceinline__ void ldsm4t(uint32_t* r, uint32_t addr) {
    asm volatile("ldmatrix.sync.aligned.m8n8.x4.trans.shared.b16 {%0,%1,%2,%3}, [%4];"
                 : "=r"(r[0]), "=r"(r[1]), "=r"(r[2]), "=r"(r[3]) : "r"(addr));
}
__device__ __forceinline__ void mma16816(float* d, const uint32_t* a,
                                         uint32_t b0, uint32_t b1) {
    asm volatile("mma.sync.aligned.m16n8k16.row.col.f32.bf16.bf16.f32 "
                 "{%0,%1,%2,%3}, {%4,%5,%6,%7}, {%8,%9}, {%0,%1,%2,%3};"
                 : "+f"(d[0]), "+f"(d[1]), "+f"(d[2]), "+f"(d[3])
                 : "r"(a[0]), "r"(a[1]), "r"(a[2]), "r"(a[3]), "r"(b0), "r"(b1));
}
__device__ __forceinline__ uint32_t swz(int row, int c) {
    return (uint32_t)(row * 64 + ((c ^ ((row >> 1) & 3)) << 4));
}
__device__ __forceinline__ uint32_t swz128(int row, int c) {
    return (uint32_t)(row * 128 + ((c ^ (row & 7)) << 4));
}
__device__ __forceinline__ void split2(float x, uint32_t& h, uint32_t& l) {
    __nv_bfloat16 hb = __float2bfloat16(x);
    __nv_bfloat16 lb = __float2bfloat16(x - __bfloat162float(hb));
    h = (uint32_t)__bfloat16_as_ushort(hb);
    l = (uint32_t)__bfloat16_as_ushort(lb);
}

// ============================ weight split kernel ==========================
struct SplitW4 { const float4* src[4]; uint2* hi[4]; uint2* lo[4]; };

__device__ __forceinline__ void split_one(const float4* src, uint2* hi,
                                          uint2* lo, int i) {
    float4 v = src[i];
    uint32_t h[4], l[4];
    split2(v.x, h[0], l[0]); split2(v.y, h[1], l[1]);
    split2(v.z, h[2], l[2]); split2(v.w, h[3], l[3]);
    uint2 ph, pl;
    ph.x = h[0] | (h[1] << 16); ph.y = h[2] | (h[3] << 16);
    pl.x = l[0] | (l[1] << 16); pl.y = l[2] | (l[3] << 16);
    hi[i] = ph; lo[i] = pl;
}
__global__ __launch_bounds__(256) void split_w4(SplitW4 p) {
    const int z = blockIdx.z;
    const int i = blockIdx.x * 512 + threadIdx.x;
    split_one(p.src[z], p.hi[z], p.lo[z], i);
    split_one(p.src[z], p.hi[z], p.lo[z], i + 256);
}

// ============================ HMMA GEMM ====================================
#define GM 128
#define GN 128
#define KCH 32
#define NST (E_/KCH)             /* 16 */
#define TILE_B (128*64)          /* 8192  */
#define STAGE_B (4*TILE_B)       /* 32768 */
#define GSMEM (2*STAGE_B)        /* 65536 */
#define AF32_B 16384
#define STAGE_F (AF32_B + 4*TILE_B)  /* 49152 */
#define GSMEM_F (2*STAGE_F)      /* 98304 */

struct Frag { float acc[4][4][4]; };

// Pass-separated MMA issue: all hh, then all hl, then A-lo reload + all lh.
// Per-accumulator op order (hh -> hl -> lh) unchanged -> bitwise identical.
__device__ __forceinline__ void gemm_stage_math(
    Frag& F, uint32_t ahB, uint32_t alB, uint32_t whB, uint32_t wlB,
    int lane, int wm, int wn)
{
#pragma unroll
    for (int ks = 0; ks < 2; ks++) {
        uint32_t af[4][4], whf[2][4], wlf[2][4];
#pragma unroll
        for (int mt = 0; mt < 4; mt++) {
            const int row = wm * 64 + mt * 16 + (lane & 15);
            const int c   = ks * 2 + (lane >> 4);
            ldsm4(af[mt], ahB + swz(row, c));
        }
#pragma unroll
        for (int np = 0; np < 2; np++) {
            const int row = wn * 32 + np * 16 + (lane & 7) + ((lane >> 4) & 1) * 8;
            const int c   = ks * 2 + ((lane >> 3) & 1);
            ldsm4(whf[np], whB + swz(row, c));
            ldsm4(wlf[np], wlB + swz(row, c));
        }
        // pass 1: hh (16 independent MMAs)
#pragma unroll
        for (int mt = 0; mt < 4; mt++)
#pragma unroll
            for (int nt = 0; nt < 4; nt++) {
                const int np = nt >> 1, o = (nt & 1) * 2;
                mma16816(F.acc[mt][nt], af[mt], whf[np][o], whf[np][o + 1]);
            }
        // pass 2: hl (each dependent on its hh, 16-instruction separation)
#pragma unroll
        for (int mt = 0; mt < 4; mt++)
#pragma unroll
            for (int nt = 0; nt < 4; nt++) {
                const int np = nt >> 1, o = (nt & 1) * 2;
                mma16816(F.acc[mt][nt], af[mt], wlf[np][o], wlf[np][o + 1]);
            }
        // pass 3: lh (A-lo reuses af registers)
#pragma unroll
        for (int mt = 0; mt < 4; mt++) {
            const int row = wm * 64 + mt * 16 + (lane & 15);
            const int c   = ks * 2 + (lane >> 4);
            ldsm4(af[mt], alB + swz(row, c));
        }
#pragma unroll
        for (int mt = 0; mt < 4; mt++)
#pragma unroll
            for (int nt = 0; nt < 4; nt++) {
                const int np = nt >> 1, o = (nt & 1) * 2;
                mma16816(F.acc[mt][nt], af[mt], whf[np][o], whf[np][o + 1]);
            }
    }
}

__device__ __forceinline__ void gemm_epilogue(
    Frag& F, const float* bias, float* out,
    __nv_bfloat16* outh, __nv_bfloat16* outl, int mode,
    int m0, int n0, int lane, int wm, int wn)
{
#pragma unroll
    for (int nt = 0; nt < 4; nt++) {
        const int gn = n0 + wn * 32 + nt * 8 + (lane & 3) * 2;
        const float2 bv = *(const float2*)(bias + gn);
#pragma unroll
        for (int mt = 0; mt < 4; mt++) {
            const int gm = m0 + wm * 64 + mt * 16 + (lane >> 2);
            float x0 = F.acc[mt][nt][0] + bv.x, x1 = F.acc[mt][nt][1] + bv.y;
            float x2 = F.acc[mt][nt][2] + bv.x, x3 = F.acc[mt][nt][3] + bv.y;
            if (mode == 0) {
                *(float2*)(out + (size_t)gm * E_ + gn)       = make_float2(x0, x1);
                *(float2*)(out + (size_t)(gm + 8) * E_ + gn) = make_float2(x2, x3);
            } else {
                uint32_t h0, l0, h1, l1, h2, l2, h3, l3;
                split2(x0, h0, l0); split2(x1, h1, l1);
                split2(x2, h2, l2); split2(x3, h3, l3);
                *(uint32_t*)(outh + (size_t)gm * E_ + gn)       = h0 | (h1 << 16);
                *(uint32_t*)(outl + (size_t)gm * E_ + gn)       = l0 | (l1 << 16);
                *(uint32_t*)(outh + (size_t)(gm + 8) * E_ + gn) = h2 | (h3 << 16);
                *(uint32_t*)(outl + (size_t)(gm + 8) * E_ + gn) = l2 | (l3 << 16);
            }
        }
    }
}

// ---- pre-split A path (O projection) --------------------------------------
__device__ __forceinline__ void gemm_issue_stage(
    uint32_t sb, int s, int m0, int n0, int tid,
    const __nv_bfloat16* Ah, const __nv_bfloat16* Al,
    const __nv_bfloat16* Wh, const __nv_bfloat16* Wl)
{
    const uint32_t base = sb + (uint32_t)(s & 1) * STAGE_B;
    const int k0 = s * KCH;
#pragma unroll
    for (int q = 0; q < 2; q++) {
        const int id  = tid * 2 + q;
        const int row = id >> 2;
        const int c   = id & 3;
        const uint32_t d = base + swz(row, c);
        const size_t ga = (size_t)(m0 + row) * E_ + k0 + c * 8;
        const size_t gw = (size_t)(n0 + row) * E_ + k0 + c * 8;
        cp16(d,              Ah + ga);
        cp16(d + TILE_B,     Al + ga);
        cp16(d + 2 * TILE_B, Wh + gw);
        cp16(d + 3 * TILE_B, Wl + gw);
    }
    asm volatile("cp.async.commit_group;" ::: "memory");
}

__global__ __launch_bounds__(256) void gemm_mma_single(
    const __nv_bfloat16* __restrict__ Ah, const __nv_bfloat16* __restrict__ Al,
    const __nv_bfloat16* __restrict__ Wh, const __nv_bfloat16* __restrict__ Wl,
    const float* __restrict__ bias, float* __restrict__ out)
{
    extern __shared__ char gsm[];
    const uint32_t sb = smem_to_u32(gsm);
    const int tid  = threadIdx.x;
    const int lane = tid & 31;
    const int wid  = tid >> 5;
    const int wm   = wid & 1;
    const int wn   = wid >> 1;
    const int m0 = blockIdx.x * GM;
    const int n0 = blockIdx.y * GN;

    Frag F;
#pragma unroll
    for (int a = 0; a < 4; a++)
#pragma unroll
        for (int b = 0; b < 4; b++)
#pragma unroll
            for (int c = 0; c < 4; c++) F.acc[a][b][c] = 0.f;

    gemm_issue_stage(sb, 0, m0, n0, tid, Ah, Al, Wh, Wl);
    gemm_issue_stage(sb, 1, m0, n0, tid, Ah, Al, Wh, Wl);

    for (int s = 0; s < NST; s++) {
        if (s < NST - 1) asm volatile("cp.async.wait_group 1;" ::: "memory");
        else             asm volatile("cp.async.wait_group 0;" ::: "memory");
        __syncthreads();
        const uint32_t base = sb + (uint32_t)(s & 1) * STAGE_B;
        gemm_stage_math(F, base, base + TILE_B,
                        base + 2 * TILE_B, base + 3 * TILE_B, lane, wm, wn);
        __syncthreads();
        if (s + 2 < NST)
            gemm_issue_stage(sb, s + 2, m0, n0, tid, Ah, Al, Wh, Wl);
    }
    gemm_epilogue(F, bias, out, nullptr, nullptr, 0, m0, n0, lane, wm, wn);
}

// ---- fp32-A path (QKV projections, in-kernel split) ----------------------
__device__ __forceinline__ void gemm_issue_stage_f32(
    uint32_t sb, int s, int m0, int n0, int tid,
    const float* A, const __nv_bfloat16* Wh, const __nv_bfloat16* Wl)
{
    const uint32_t base = sb + (uint32_t)(s & 1) * STAGE_F;
    const int k0 = s * KCH;
#pragma unroll
    for (int q = 0; q < 4; q++) {
        const int id  = tid + q * 256;
        const int row = id >> 3, c = id & 7;
        cp16(base + swz128(row, c),
             A + (size_t)(m0 + row) * E_ + k0 + c * 4);
    }
#pragma unroll
    for (int q = 0; q < 2; q++) {
        const int id  = tid * 2 + q;
        const int row = id >> 2, c = id & 3;
        const size_t gw = (size_t)(n0 + row) * E_ + k0 + c * 8;
        cp16(base + AF32_B + 2 * TILE_B + swz(row, c), Wh + gw);
        cp16(base + AF32_B + 3 * TILE_B + swz(row, c), Wl + gw);
    }
    asm volatile("cp.async.commit_group;" ::: "memory");
}

struct GemmF3 {
    const float* A[3];
    const __nv_bfloat16* Wh[3]; const __nv_bfloat16* Wl[3];
    const float* bias[3];
    __nv_bfloat16* outh[3]; __nv_bfloat16* outl[3];
};

__global__ __launch_bounds__(256) void gemm_f32_b3(GemmF3 p) {
    extern __shared__ char gsm[];
    const uint32_t sb = smem_to_u32(gsm);
    const int z = blockIdx.z;
    const float* A = p.A[z];
    const __nv_bfloat16* Wh = p.Wh[z];
    const __nv_bfloat16* Wl = p.Wl[z];
    const int tid  = threadIdx.x;
    const int lane = tid & 31;
    const int wid  = tid >> 5;
    const int wm   = wid & 1;
    const int wn   = wid >> 1;
    const int m0 = blockIdx.x * GM;
    const int n0 = blockIdx.y * GN;

    Frag F;
#pragma unroll
    for (int a = 0; a < 4; a++)
#pragma unroll
        for (int b = 0; b < 4; b++)
#pragma unroll
            for (int c = 0; c < 4; c++) F.acc[a][b][c] = 0.f;

    gemm_issue_stage_f32(sb, 0, m0, n0, tid, A, Wh, Wl);
    gemm_issue_stage_f32(sb, 1, m0, n0, tid, A, Wh, Wl);

    const int crow = tid >> 1, chalf = tid & 1;

    for (int s = 0; s < NST; s++) {
        if (s < NST - 1) asm volatile("cp.async.wait_group 1;" ::: "memory");
        else             asm volatile("cp.async.wait_group 0;" ::: "memory");
        __syncthreads();

        char* bufp = gsm + (size_t)(s & 1) * STAGE_F;
        {
            float4 f[4];
#pragma unroll
            for (int cc = 0; cc < 4; cc++)
                f[cc] = *(const float4*)(bufp + swz128(crow, chalf * 4 + cc));
            const float* fv = &f[0].x;
#pragma unroll
            for (int pp = 0; pp < 2; pp++) {
                uint32_t ph[4], pl[4];
#pragma unroll
                for (int e = 0; e < 4; e++) {
                    uint32_t h0, l0, h1, l1;
                    split2(fv[pp * 8 + e * 2 + 0], h0, l0);
                    split2(fv[pp * 8 + e * 2 + 1], h1, l1);
                    ph[e] = h0 | (h1 << 16);
                    pl[e] = l0 | (l1 << 16);
                }
                const uint32_t co = swz(crow, chalf * 2 + pp);
                *(uint4*)(bufp + AF32_B + co) =
                    make_uint4(ph[0], ph[1], ph[2], ph[3]);
                *(uint4*)(bufp + AF32_B + TILE_B + co) =
                    make_uint4(pl[0], pl[1], pl[2], pl[3]);
            }
        }
        __syncthreads();

        const uint32_t base = sb + (uint32_t)(s & 1) * STAGE_F;
        gemm_stage_math(F, base + AF32_B, base + AF32_B + TILE_B,
                        base + AF32_B + 2 * TILE_B, base + AF32_B + 3 * TILE_B,
                        lane, wm, wn);
        __syncthreads();
        if (s + 2 < NST)
            gemm_issue_stage_f32(sb, s + 2, m0, n0, tid, A, Wh, Wl);
    }
    gemm_epilogue(F, p.bias[z], nullptr, p.outh[z], p.outl[z], 1,
                  m0, n0, lane, wm, wn);
}

// ============================ sparse attention =============================
#define QT 64
#define SCLD 200
#define ATTN_SMEM (32768 + QT*SCLD*4)   /* 83968 B -> 2 CTAs/SM */

__global__ __launch_bounds__(256) void attn_tiled(
    float* __restrict__ attn_out,
    __nv_bfloat16* __restrict__ ctx_hi, __nv_bfloat16* __restrict__ ctx_lo,
    const __nv_bfloat16* __restrict__ qh, const __nv_bfloat16* __restrict__ ql,
    const __nv_bfloat16* __restrict__ kh, const __nv_bfloat16* __restrict__ kl,
    const __nv_bfloat16* __restrict__ vh, const __nv_bfloat16* __restrict__ vl)
{
    extern __shared__ char smraw[];
    const uint32_t sb = smem_to_u32(smraw);
    float* sc = (float*)(smraw + 32768);

    const int tid  = threadIdx.x;
    const int lane = tid & 31;
    const int wid  = tid >> 5;
    const int wm   = wid & 3;
    const int wn   = wid >> 2;
    const int qt   = blockIdx.x;
    const int h    = blockIdx.y;
    const int z    = blockIdx.z;

    const int q0     = qt * QT;
    const int we     = q0 + QT - 1;
    const int wstart = (q0 >= WINDOW) ? (q0 - WINDOW) : 0;
    const int Ncs    = wstart >> 2;
    const int NU     = Ncs + (we - wstart + 1);
    const int nch    = (NU + 31) >> 5;

    const size_t tokBase = ((size_t)z * S_) * E_ + h * HD_;

    for (int t = tid; t < 512; t += 256) {
        const int r = t >> 3, c = t & 7;
        const size_t g = tokBase + (size_t)(q0 + r) * E_ + c * 8;
        const uint32_t d = sb + swz128(r, c);
        cp16(d, qh + g);
        cp16(d + 8192, ql + g);
    }
    asm volatile("cp.async.commit_group;" ::: "memory");

    auto issue_kv = [&](const __nv_bfloat16* xh, const __nv_bfloat16* xl,
                        int ch) {
        const int uc0 = ch << 5;
        const uint32_t buf = sb + 16384 + (uint32_t)(ch & 1) * 8192;
        for (int t = tid; t < 256; t += 256) {
            const int r = t >> 3, c = t & 7;
            const int u = uc0 + r;
            int j = 0;
            if (u < NU) j = (u < Ncs) ? (u << 2) : (wstart + u - Ncs);
            const size_t g = tokBase + (size_t)j * E_ + c * 8;
            cp16(buf + swz128(r, c), xh + g);
            cp16(buf + 4096 + swz128(r, c), xl + g);
        }
        asm volatile("cp.async.commit_group;" ::: "memory");
    };

    // ---- scores ------------------------------------------------------------
    const float NEGINF = __int_as_float(0xff800000);
    issue_kv(kh, kl, 0);
    for (int ch = 0; ch < nch; ch++) {
        if (ch + 1 < nch) {
            issue_kv(kh, kl, ch + 1);
            asm volatile("cp.async.wait_group 1;" ::: "memory");
        } else {
            asm volatile("cp.async.wait_group 0;" ::: "memory");
        }
        __syncthreads();

        const int uc0 = ch << 5;
        const uint32_t kB = sb + 16384 + (uint32_t)(ch & 1) * 8192;

        float acc[2][4];
#pragma unroll
        for (int a = 0; a < 2; a++)
#pragma unroll
            for (int b = 0; b < 4; b++) acc[a][b] = 0.f;

#pragma unroll
        for (int kk = 0; kk < 4; kk++) {
            uint32_t ah[4], al[4], bh[4], bl[4];
            {
                const int row = wm * 16 + (lane & 15);
                const int c   = kk * 2 + (lane >> 4);
                ldsm4(ah, sb + swz128(row, c));
                ldsm4(al, sb + 8192 + swz128(row, c));
            }
            {
                const int row = wn * 16 + (lane & 7) + ((lane >> 4) & 1) * 8;
                const int c   = kk * 2 + ((lane >> 3) & 1);
                ldsm4(bh, kB + swz128(row, c));
                ldsm4(bl, kB + 4096 + swz128(row, c));
            }
            // pass-separated: hh x2, hl x2, lh x2
#pragma unroll
            for (int nt = 0; nt < 2; nt++)
                mma16816(acc[nt], ah, bh[nt * 2], bh[nt * 2 + 1]);
#pragma unroll
            for (int nt = 0; nt < 2; nt++)
                mma16816(acc[nt], ah, bl[nt * 2], bl[nt * 2 + 1]);
#pragma unroll
            for (int nt = 0; nt < 2; nt++)
                mma16816(acc[nt], al, bh[nt * 2], bh[nt * 2 + 1]);
        }

        const int r0 = wm * 16 + (lane >> 2);
#pragma unroll
        for (int nt = 0; nt < 2; nt++) {
            const int uc = uc0 + wn * 16 + nt * 8 + (lane & 3) * 2;
            if (uc < NU) {
                const int ja = (uc < Ncs) ? (uc << 2) : (wstart + uc - Ncs);
                const int jb = (uc + 1 < Ncs) ? ((uc + 1) << 2)
                                              : (wstart + uc + 1 - Ncs);
#pragma unroll
                for (int h2 = 0; h2 < 2; h2++) {
                    const int row = r0 + h2 * 8;
                    const int i   = q0 + row;
                    const bool oka = (ja <= i) && ((ja >= i - WINDOW) || ((ja & 3) == 0));
                    const bool okb = (jb <= i) && ((jb >= i - WINDOW) || ((jb & 3) == 0));
                    float2 st;
                    st.x = oka ? acc[nt][h2 * 2 + 0] * 0.125f : NEGINF;
                    st.y = okb ? acc[nt][h2 * 2 + 1] * 0.125f : NEGINF;
                    *(float2*)(sc + row * SCLD + uc) = st;
                }
            }
        }
        __syncthreads();
    }

    // ---- softmax -----------------------------------------------------------
    {
        const int row = tid >> 2;
        const int ln  = tid & 3;
        float* srow = sc + row * SCLD;
        const int nv = NU >> 2;
        float m = NEGINF;
        for (int q = ln; q < nv; q += 4) {
            const float4 v = ((const float4*)srow)[q];
            m = fmaxf(m, fmaxf(fmaxf(v.x, v.y), fmaxf(v.z, v.w)));
        }
        m = fmaxf(m, __shfl_xor_sync(0xffffffffu, m, 1));
        m = fmaxf(m, __shfl_xor_sync(0xffffffffu, m, 2));
        float sum = 0.f;
        for (int q = ln; q < nv; q += 4) {
            float4 v = ((const float4*)srow)[q];
            v.x = __expf(v.x - m); v.y = __expf(v.y - m);
            v.z = __expf(v.z - m); v.w = __expf(v.w - m);
            ((float4*)srow)[q] = v;
            sum += v.x + v.y + v.z + v.w;
        }
        sum += __shfl_xor_sync(0xffffffffu, sum, 1);
        sum += __shfl_xor_sync(0xffffffffu, sum, 2);
        const float inv = 1.f / sum;
        for (int q = ln; q < nv; q += 4) {
            float4 v = ((const float4*)srow)[q];
            v.x *= inv; v.y *= inv; v.z *= inv; v.w *= inv;
            ((float4*)srow)[q] = v;
        }
    }
    __syncthreads();

    issue_kv(vh, vl, 0);

    // ---- dense attn write --------------------------------------------------
    {
        const int b = z / C_, c = z % C_;
        float* abase = attn_out +
            ((((size_t)(b * H_ + h) * C_ + c) * S_ + q0) * (size_t)S_);
        for (int t = tid; t < QT * (S_ / 4); t += 256) {
            const int r  = t >> 7;
            const int j0 = (t & 127) << 2;
            const float* srow = sc + r * SCLD;
            float4 v = make_float4(0.f, 0.f, 0.f, 0.f);
            if (j0 <= we) {
                if (j0 >= wstart)
                    v = *(const float4*)(srow + Ncs + j0 - wstart);
                else
                    v.x = srow[j0 >> 2];
            }
            *(float4*)(abase + (size_t)r * S_ + j0) = v;
        }
    }

    // ---- context -----------------------------------------------------------
    float cacc[4][4];
#pragma unroll
    for (int a = 0; a < 4; a++)
#pragma unroll
        for (int b = 0; b < 4; b++) cacc[a][b] = 0.f;

    for (int ch = 0; ch < nch; ch++) {
        const int uc0 = ch << 5;
        if (ch + 1 < nch) issue_kv(vh, vl, ch + 1);

        for (int t = tid; t < 256; t += 256) {
            const int row = t >> 2, cg = t & 3;
            const int u0 = uc0 + cg * 8;
            float4 pa = make_float4(0.f, 0.f, 0.f, 0.f);
            float4 pb = make_float4(0.f, 0.f, 0.f, 0.f);
            if (u0 < NU) {
                pa = *(const float4*)(sc + row * SCLD + u0);
                pb = *(const float4*)(sc + row * SCLD + u0 + 4);
            }
            const float pv[8] = {pa.x, pa.y, pa.z, pa.w, pb.x, pb.y, pb.z, pb.w};
            uint32_t hp[4], lp[4];
#pragma unroll
            for (int pr = 0; pr < 4; pr++) {
                uint32_t h0, l0, h1, l1;
                split2(pv[pr * 2 + 0], h0, l0);
                split2(pv[pr * 2 + 1], h1, l1);
                hp[pr] = h0 | (h1 << 16);
                lp[pr] = l0 | (l1 << 16);
            }
            *(uint4*)(smraw + swz(row, cg))        = make_uint4(hp[0], hp[1], hp[2], hp[3]);
            *(uint4*)(smraw + 8192 + swz(row, cg)) = make_uint4(lp[0], lp[1], lp[2], lp[3]);
        }
        if (ch + 1 < nch)
            asm volatile("cp.async.wait_group 1;" ::: "memory");
        else
            asm volatile("cp.async.wait_group 0;" ::: "memory");
        __syncthreads();

        const uint32_t vB = sb + 16384 + (uint32_t)(ch & 1) * 8192;
#pragma unroll
        for (int kk = 0; kk < 2; kk++) {
            uint32_t ah[4], al[4], bh[2][4], bl[2][4];
            {
                const int row = wm * 16 + (lane & 15);
                const int c   = kk * 2 + (lane >> 4);
                ldsm4(ah, sb + swz(row, c));
                ldsm4(al, sb + 8192 + swz(row, c));
            }
#pragma unroll
            for (int np = 0; np < 2; np++) {
                const int row = kk * 16 + (lane & 15);
                const int c   = wn * 4 + np * 2 + (lane >> 4);
                ldsm4t(bh[np], vB + swz128(row, c));
                ldsm4t(bl[np], vB + 4096 + swz128(row, c));
            }
            // pass-separated: hh x4, hl x4, lh x4
#pragma unroll
            for (int nt = 0; nt < 4; nt++) {
                const int np = nt >> 1, o = (nt & 1) * 2;
                mma16816(cacc[nt], ah, bh[np][o], bh[np][o + 1]);
            }
#pragma unroll
            for (int nt = 0; nt < 4; nt++) {
                const int np = nt >> 1, o = (nt & 1) * 2;
                mma16816(cacc[nt], ah, bl[np][o], bl[np][o + 1]);
            }
#pragma unroll
            for (int nt = 0; nt < 4; nt++) {
                const int np = nt >> 1, o = (nt & 1) * 2;
                mma16816(cacc[nt], al, bh[np][o], bh[np][o + 1]);
            }
        }
        __syncthreads();
    }

    // ---- epilogue ----------------------------------------------------------
    {
        const int r0 = wm * 16 + (lane >> 2);
#pragma unroll
        for (int nt = 0; nt < 4; nt++) {
            const int d0 = wn * 32 + nt * 8 + (lane & 3) * 2;
#pragma unroll
            for (int h2 = 0; h2 < 2; h2++) {
                const int i = q0 + r0 + h2 * 8;
                const size_t base = tokBase + (size_t)i * E_ + d0;
                uint32_t h0, l0, h1, l1;
                split2(cacc[nt][h2 * 2 + 0], h0, l0);
                split2(cacc[nt][h2 * 2 + 1], h1, l1);
                *(uint32_t*)(ctx_hi + base) = h0 | (h1 << 16);
                *(uint32_t*)(ctx_lo + base) = l0 | (l1 << 16);
            }
        }
    }
}

// ===========================================================================
extern "C" void kernel_launch(void* const* d_in, const int* in_sizes, int n_in,
                              void* d_out, int out_size)
{
    const float* query = (const float*)d_in[0];
    const float* key_  = (const float*)d_in[1];
    const float* value = (const float*)d_in[2];
    const float* Wq = (const float*)d_in[3];
    const float* bq = (const float*)d_in[4];
    const float* Wk = (const float*)d_in[5];
    const float* bk = (const float*)d_in[6];
    const float* Wv = (const float*)d_in[7];
    const float* bv = (const float*)d_in[8];
    const float* Wo = (const float*)d_in[9];
    const float* bo = (const float*)d_in[10];

    float* out  = (float*)d_out;
    float* attn = out + (size_t)NTOK * E_;

    __nv_bfloat16 *inh, *inl, *Wh4, *Wl4, *qh, *ql, *kh, *kl, *vh, *vl;
    cudaGetSymbolAddress((void**)&inh, g_inh);
    cudaGetSymbolAddress((void**)&inl, g_inl);
    cudaGetSymbolAddress((void**)&Wh4, g_Wh4);
    cudaGetSymbolAddress((void**)&Wl4, g_Wl4);
    cudaGetSymbolAddress((void**)&qh, g_qh);
    cudaGetSymbolAddress((void**)&ql, g_ql);
    cudaGetSymbolAddress((void**)&kh, g_kh);
    cudaGetSymbolAddress((void**)&kl, g_kl);
    cudaGetSymbolAddress((void**)&vh, g_vh);
    cudaGetSymbolAddress((void**)&vl, g_vl);

    cudaFuncSetAttribute(attn_tiled,
        cudaFuncAttributeMaxDynamicSharedMemorySize, ATTN_SMEM);
    cudaFuncSetAttribute(gemm_f32_b3,
        cudaFuncAttributeMaxDynamicSharedMemorySize, GSMEM_F);
    cudaFuncSetAttribute(gemm_mma_single,
        cudaFuncAttributeMaxDynamicSharedMemorySize, GSMEM);

    const size_t WE = (size_t)E_ * E_;
    const int NW4 = E_ * E_ / 4;

    SplitW4 sw;
    sw.src[0] = (const float4*)Wq; sw.src[1] = (const float4*)Wk;
    sw.src[2] = (const float4*)Wv; sw.src[3] = (const float4*)Wo;
    for (int z = 0; z < 4; z++) {
        sw.hi[z] = (uint2*)(Wh4 + z * WE);
        sw.lo[z] = (uint2*)(Wl4 + z * WE);
    }
    split_w4<<<dim3(NW4 / 512, 1, 4), 256>>>(sw);

    GemmF3 gf;
    gf.A[0] = query; gf.A[1] = key_; gf.A[2] = value;
    __nv_bfloat16* oh[3] = {qh, kh, vh};
    __nv_bfloat16* ol[3] = {ql, kl, vl};
    const float* bs[3] = {bq, bk, bv};
    for (int z = 0; z < 3; z++) {
        gf.Wh[z] = Wh4 + z * WE;  gf.Wl[z] = Wl4 + z * WE;
        gf.bias[z] = bs[z];
        gf.outh[z] = oh[z];  gf.outl[z] = ol[z];
    }
    gemm_f32_b3<<<dim3(NTOK / GM, E_ / GN, 3), 256, GSMEM_F>>>(gf);

    dim3 agrid(S_ / QT, H_, B_ * C_);
    attn_tiled<<<agrid, 256, ATTN_SMEM>>>(attn, inh, inl,
                                          qh, ql, kh, kl, vh, vl);

    gemm_mma_single<<<dim3(NTOK / GM, E_ / GN), 256, GSMEM>>>(
        inh, inl, Wh4 + 3 * WE, Wl4 + 3 * WE, bo, out);
}